// round 12
// baseline (speedup 1.0000x reference)
#include <cuda_runtime.h>
#include <cstdint>
#include <cstddef>

#define NXD  128
#define TLEN 4096
#define NB   32
#define LCH  32
#define KCH  128
#define NCH  (NB*KCH)     // 4096 (batch, chunk) rows
#define OMD  2048         // LCH*64 : Omega dim, Y cols per (b,chunk) row
#define STG_F 8192        // floats per pipeline stage (A 4096 + B 4096)

// ---------------- static device workspaces ----------------------------------
__device__ float g_E[NXD*NXD];
__device__ float g_F[NXD*NXD];
__device__ float g_chain[7*NXD*NXD];          // A^(2^s), s=0..5 used
__device__ float g_Pstack[OMD*NXD];           // P_i = C A^i (raw fp32), 2048x128
__device__ float g_Ptf[OMD*NXD];              // P permuted + tf32
__device__ float g_GBwide[NXD*OMD];           // [A^m B] blocks (128 x 2048)
__device__ float g_BinjT[NXD*OMD];            // injection op^T, permuted+tf32
__device__ float g_Hstack[OMD*64];            // H_m = C A^m B (2048 x 64)
__device__ float g_Om[(size_t)OMD*OMD];       // Omega, permuted+tf32 (16MB)
__device__ float g_Utf[(size_t)NB*TLEN*64];   // U permuted + tf32 (32MB)
__device__ float g_V[NCH*NXD];
__device__ float g_Xp[NCH*NXD];               // chunk states, permuted+tf32
__device__ float g_Vpart[4*NCH*NXD];

// ---------------- helpers ----------------------------------------------------
__device__ __forceinline__ float to_tf32(float x) {
    uint32_t u;
    asm("cvt.rna.tf32.f32 %0, %1;" : "=r"(u) : "f"(x));
    return __uint_as_float(u);
}
__device__ __forceinline__ uint32_t smem_u32(const void* p) {
    uint32_t a;
    asm("{ .reg .u64 t; cvta.to.shared.u64 t, %1; cvt.u32.u64 %0, t; }"
        : "=r"(a) : "l"(p));
    return a;
}
__device__ __forceinline__ void mma8(float* c, float a0, float a1, float a2,
                                     float a3, float b0, float b1) {
    asm volatile(
        "mma.sync.aligned.m16n8k8.row.col.f32.tf32.tf32.f32 "
        "{%0,%1,%2,%3}, {%4,%5,%6,%7}, {%8,%9}, {%0,%1,%2,%3};"
        : "+f"(c[0]), "+f"(c[1]), "+f"(c[2]), "+f"(c[3])
        : "r"(__float_as_uint(a0)), "r"(__float_as_uint(a1)),
          "r"(__float_as_uint(a2)), "r"(__float_as_uint(a3)),
          "r"(__float_as_uint(b0)), "r"(__float_as_uint(b1)));
}
__device__ __forceinline__ void cp16(uint32_t dst, const float* src) {
    asm volatile("cp.async.cg.shared.global [%0], [%1], 16;"
                 :: "r"(dst), "l"(src));
}
// permutation: source k (within 32-block) stored at pos (k%4)*8 + k/4
__device__ __forceinline__ int kperm(int j) { return ((j & 3) << 3) | (j >> 2); }

// ---------------- E, F from M ------------------------------------------------
__global__ void ef_kernel(const float* __restrict__ M)
{
    __shared__ float s0i[32][33], s1i[32][33], s0j[32][33], s1j[32][33];
    int tx = threadIdx.x, ty = threadIdx.y;
    int i0 = blockIdx.y * 32, j0 = blockIdx.x * 32;
    float e0 = 0.f, e1 = 0.f, f = 0.f;
    for (int kt = 0; kt < 256; kt += 32) {
        s0i[ty][tx] = M[(i0 + ty) * 256 + kt + tx];
        s1i[ty][tx] = M[(128 + i0 + ty) * 256 + kt + tx];
        s0j[ty][tx] = M[(j0 + ty) * 256 + kt + tx];
        s1j[ty][tx] = M[(128 + j0 + ty) * 256 + kt + tx];
        __syncthreads();
        #pragma unroll
        for (int kk = 0; kk < 32; kk++) {
            float a0 = s0i[ty][kk], a1 = s1i[ty][kk];
            float b0 = s0j[tx][kk], b1 = s1j[tx][kk];
            e0 += a0 * b0; e1 += a1 * b1; f += a1 * b0;
        }
        __syncthreads();
    }
    int i = i0 + ty, j = j0 + tx;
    float e = 0.5f * (e0 + e1);
    if (i == j) e += 1e-9f;
    g_E[i * NXD + j] = e;
    g_F[i * NXD + j] = f;
}

// ---------------- register-resident Gauss-Jordan, 1024 threads ---------------
// cq = t>>7 in 0..7 owns cols [cq*32, cq*32+32) of the augmented [E|F] row
// rq = t&127. Pivot col k (k<128) is owned by group k>>5. One barrier/pivot,
// parity double-buffered prow/sfac.
__global__ void __launch_bounds__(1024) solve_kernel()
{
    __shared__ float4 prow4[2][64];      // pivot row (unscaled), 256 floats
    __shared__ float  sfac[2][128];      // W[rq][k] per row
    int t = threadIdx.x;
    int cq = t >> 7, rq = t & 127;

    float4 w[8];
    {
        const float* src = (cq < 4) ? (g_E + rq * 128 + cq * 32)
                                    : (g_F + rq * 128 + (cq - 4) * 32);
        #pragma unroll
        for (int i = 0; i < 8; i++) w[i] = ((const float4*)src)[i];
    }

    for (int k = 0; k < 128; k++) {
        int b = k & 1;
        if (cq == (k >> 5)) {
            int jf4 = (k >> 2) & 7, jc = k & 3;
            float4 v = w[0];
            #pragma unroll
            for (int i = 1; i < 8; i++) if (jf4 == i) v = w[i];
            float f = (jc == 0) ? v.x : (jc == 1) ? v.y
                    : (jc == 2) ? v.z : v.w;
            sfac[b][rq] = f;
        }
        if (rq == k) {
            #pragma unroll
            for (int i = 0; i < 8; i++) prow4[b][cq * 8 + i] = w[i];
        }
        __syncthreads();

        float pv = sfac[b][k];
        float r;
        asm("rcp.approx.f32 %0, %1;" : "=f"(r) : "f"(pv));
        r = r * (2.0f - pv * r);
        r = r * (2.0f - pv * r);

        if (rq == k) {
            #pragma unroll
            for (int i = 0; i < 8; i++) {
                w[i].x *= r; w[i].y *= r; w[i].z *= r; w[i].w *= r;
            }
        } else {
            float factor = sfac[b][rq] * r;
            #pragma unroll
            for (int i = 0; i < 8; i++) {
                float4 p = prow4[b][cq * 8 + i];
                w[i].x -= factor * p.x; w[i].y -= factor * p.y;
                w[i].z -= factor * p.z; w[i].w -= factor * p.w;
            }
        }
    }

    if (cq >= 4) {
        float* dst = g_chain + rq * 128 + (cq - 4) * 32;
        #pragma unroll
        for (int i = 0; i < 8; i++) ((float4*)dst)[i] = w[i];
    }
}

// ---------------- generic tiled GEMM C = A*B (row-major) for H ---------------
__global__ void mm_nn(float* __restrict__ Cc, const float* __restrict__ A,
                      const float* __restrict__ B,
                      int Mm, int Nn, int Kk, int lda, int ldb, int ldc)
{
    __shared__ float As[16][17], Bs[16][17];
    int tx = threadIdx.x, ty = threadIdx.y;
    int row = blockIdx.y * 16 + ty, col = blockIdx.x * 16 + tx;
    float acc = 0.f;
    for (int k0 = 0; k0 < Kk; k0 += 16) {
        As[ty][tx] = (row < Mm) ? A[row * lda + k0 + tx] : 0.f;
        Bs[ty][tx] = (col < Nn) ? B[(k0 + ty) * ldb + col] : 0.f;
        __syncthreads();
        #pragma unroll
        for (int kk = 0; kk < 16; kk++) acc += As[ty][kk] * Bs[kk][tx];
        __syncthreads();
    }
    if (row < Mm && col < Nn) Cc[row * ldc + col] = acc;
}

// ---------------- fused doubling step: chain^2, GB extend, P extend ----------
__global__ void fused_double(int s)
{
    int w = 64 << s;
    int t1 = w >> 1;
    int bid = blockIdx.x;
    const float* chain_s = g_chain + s * 16384;
    const float *Ain, *Bin; float* Cout;
    int bx, by, lda, ldb, ldc;
    if (bid < 64) {
        bx = bid & 7; by = bid >> 3;
        Ain = chain_s; Bin = chain_s; Cout = g_chain + (s + 1) * 16384;
        lda = 128; ldb = 128; ldc = 128;
    } else if (bid < 64 + t1) {
        int r = bid - 64; int nt = w >> 4;
        bx = r % nt; by = r / nt;
        Ain = chain_s; Bin = g_GBwide; Cout = g_GBwide + w;
        lda = 128; ldb = OMD; ldc = OMD;
    } else {
        int r = bid - 64 - t1;
        bx = r & 7; by = r >> 3;
        Ain = g_Pstack; Bin = chain_s; Cout = g_Pstack + w * 128;
        lda = 128; ldb = 128; ldc = 128;
    }
    __shared__ float As[16][17], Bs[16][17];
    int tx = threadIdx.x, ty = threadIdx.y;
    int row = by * 16 + ty, col = bx * 16 + tx;
    float acc = 0.f;
    for (int k0 = 0; k0 < 128; k0 += 16) {
        As[ty][tx] = Ain[row * lda + k0 + tx];
        Bs[ty][tx] = Bin[(k0 + ty) * ldb + col];
        __syncthreads();
        #pragma unroll
        for (int kk = 0; kk < 16; kk++) acc += As[ty][kk] * Bs[kk][tx];
        __syncthreads();
    }
    Cout[row * ldc + col] = acc;
}

// ---------------- small helpers ---------------------------------------------
__global__ void copy_kernel(float* __restrict__ dst, const float* __restrict__ src, int n)
{
    int i = blockIdx.x * blockDim.x + threadIdx.x;
    if (i < n) dst[i] = src[i];
}

__global__ void copy_bmat(const float* __restrict__ Bm)
{
    int i = blockIdx.x * blockDim.x + threadIdx.x;
    if (i < 128 * 64) {
        int r = i >> 6, c = i & 63;
        g_GBwide[r * OMD + c] = Bm[i];
    }
}

// permute within 32-float blocks + tf32 round
__global__ void permute_tf32(float* __restrict__ dst, const float* __restrict__ src,
                             int n)
{
    int i = blockIdx.x * blockDim.x + threadIdx.x;
    if (i >= n) return;
    int q = i & 31;
    int j = ((q & 7) << 2) | (q >> 3);       // inverse permutation
    dst[i] = to_tf32(src[(i - q) + j]);
}

// BinjT[n][perm(q)] = tf32( (A^(31-j) B)[n][uu] ),  q = j*64+uu
__global__ void build_binjT()
{
    int n = blockIdx.x;
    for (int q = threadIdx.x; q < OMD; q += blockDim.x) {
        float v = g_GBwide[n * OMD + (31 - (q >> 6)) * 64 + (q & 63)];
        g_BinjT[n * OMD + (q & ~31) + kperm(q & 31)] = to_tf32(v);
    }
}

// Om[p][perm(q)] = (j<i) ? tf32(H_{i-1-j}[o][uu]) : 0   p=(i,o), i,j 0..31
__global__ void build_om()
{
    int p = blockIdx.x;
    int i = p >> 6, o = p & 63;
    size_t base = (size_t)p * OMD;
    for (int q = threadIdx.x; q < OMD; q += blockDim.x) {
        int j = q >> 6, uu = q & 63;
        float v = 0.f;
        if (j < i) v = to_tf32(g_Hstack[(((i - 1 - j) << 6) + o) * 64 + uu]);
        g_Om[base + (q & ~31) + kperm(q & 31)] = v;
    }
}

__global__ void reduce_v()
{
    int i = blockIdx.x * blockDim.x + threadIdx.x;
    if (i < NCH * NXD) {
        float s = 0.f;
        #pragma unroll
        for (int z = 0; z < 4; z++) s += g_Vpart[(size_t)z * NCH * NXD + i];
        g_V[i] = s;
    }
}

// ---------------- chunk-level scan (A^32, 127 steps) -------------------------
__global__ void __launch_bounds__(128) chunk_scan(const float* __restrict__ x0)
{
    extern __shared__ float At[];        // 128*129 floats
    __shared__ float xs[128];
    int b = blockIdx.x, n = threadIdx.x;
    int np = (n & ~31) | kperm(n & 31);
    const float* A32 = g_chain + 5 * NXD * NXD;
    for (int idx = n; idx < 128 * 128; idx += 128) {
        int row = idx >> 7, col = idx & 127;
        At[col * 129 + row] = A32[idx];
    }
    xs[n] = x0[n];
    __syncthreads();
    g_Xp[(b * KCH + 0) * NXD + np] = to_tf32(xs[n]);
    for (int k = 0; k < KCH - 1; k++) {
        float acc = g_V[(b * KCH + k) * NXD + n];
        #pragma unroll 8
        for (int m = 0; m < 128; m++) acc += At[m * 129 + n] * xs[m];
        __syncthreads();
        xs[n] = acc;
        __syncthreads();
        g_Xp[(b * KCH + k + 1) * NXD + np] = to_tf32(acc);
    }
}

// ---------------- main GEMM via mma.sync tf32, 16 warps, 2 CTAs/SM -----------
// Y(4096 x 2048) = Uc * Om^T (triangular cutoff) + X * P^T
// CTA 128x128, 16 warps (4x4), warp tile 32x32, BK=32, 3-stage cp.async.
__global__ void __launch_bounds__(512, 2) gemm_main_mma(float* __restrict__ out)
{
    extern __shared__ float sm[];
    int t = threadIdx.x, wid = t >> 5, lane = t & 31;
    int ct = 15 - blockIdx.x, rt = blockIdx.y;
    int mwarp = wid >> 2, nwarp = wid & 3;
    int mbase = mwarp * 32, nbase = nwarp * 32;
    int gr = lane >> 2, gc = lane & 3;

    int kend = (2 * ct + 1) * 64;
    int nU = kend >> 5;
    int NC = nU + 4;

    int ft = t & 255;
    int fr = ft >> 1, fs = ft & 1;
    bool isB = t >= 256;
    const float* g0;
    const float* g1;
    if (!isB) {
        g0 = g_Utf + (size_t)(rt * 128 + fr) * OMD + fs * 16;
        g1 = g_Xp  + (rt * 128 + fr) * NXD + fs * 16;
    } else {
        g0 = g_Om  + (size_t)(ct * 128 + fr) * OMD + fs * 16;
        g1 = g_Ptf + (ct * 128 + fr) * NXD + fs * 16;
    }

    int ubase = (4 * fs) ^ (fr & 7);
    uint32_t d0 = smem_u32(sm + (isB ? 4096 : 0) + fr * 32 + ubase * 4);

    auto issue = [&](int jc) {
        const float* s = (jc < nU) ? (g0 + jc * 32) : (g1 + (jc - nU) * 32);
        uint32_t da = d0 + (uint32_t)(jc % 3) * 32768u;
        #pragma unroll
        for (int i = 0; i < 4; i++) cp16(da ^ (i << 4), s + i * 4);
        asm volatile("cp.async.commit_group;" ::: "memory");
    };

    float acc[2][4][4] = {};
    int su = (2 * gc) ^ gr;

    issue(0);
    if (NC > 1) issue(1);

    for (int ic = 0; ic < NC; ic++) {
        if (ic + 2 < NC) { issue(ic + 2);
            asm volatile("cp.async.wait_group 2;" ::: "memory"); }
        else if (ic + 1 < NC)
            asm volatile("cp.async.wait_group 1;" ::: "memory");
        else
            asm volatile("cp.async.wait_group 0;" ::: "memory");
        __syncthreads();

        const float4* As4 = (const float4*)(sm + (ic % 3) * STG_F);
        const float4* Bs4 = As4 + 1024;
        #pragma unroll
        for (int h = 0; h < 2; h++) {
            int suh = su ^ h;
            float4 av[2][2], bv[4];
            #pragma unroll
            for (int mt = 0; mt < 2; mt++) {
                av[mt][0] = As4[(mbase + mt * 16 + gr) * 8 + suh];
                av[mt][1] = As4[(mbase + mt * 16 + 8 + gr) * 8 + suh];
            }
            #pragma unroll
            for (int nt = 0; nt < 4; nt++)
                bv[nt] = Bs4[(nbase + nt * 8 + gr) * 8 + suh];
            #pragma unroll
            for (int s2 = 0; s2 < 2; s2++) {
                #pragma unroll
                for (int mt = 0; mt < 2; mt++) {
                    const float* a0p = (const float*)&av[mt][0];
                    const float* a1p = (const float*)&av[mt][1];
                    #pragma unroll
                    for (int nt = 0; nt < 4; nt++) {
                        const float* bp = (const float*)&bv[nt];
                        mma8(acc[mt][nt], a0p[2*s2], a1p[2*s2],
                             a0p[2*s2+1], a1p[2*s2+1], bp[2*s2], bp[2*s2+1]);
                    }
                }
            }
        }
        __syncthreads();
    }

    // epilogue: out rows are contiguous 2048-float spans
    #pragma unroll
    for (int mt = 0; mt < 2; mt++) {
        int rg0 = rt * 128 + mbase + mt * 16 + gr;
        int rg1 = rg0 + 8;
        float* base0 = out + (size_t)rg0 * OMD;
        float* base1 = out + (size_t)rg1 * OMD;
        #pragma unroll
        for (int nt = 0; nt < 4; nt++) {
            int p = ct * 128 + nbase + nt * 8 + 2 * gc;
            float2 w0 = {acc[mt][nt][0], acc[mt][nt][1]};
            float2 w1 = {acc[mt][nt][2], acc[mt][nt][3]};
            *(float2*)(base0 + p) = w0;
            *(float2*)(base1 + p) = w1;
        }
    }
}

// ---------------- injection GEMM via mma, 16 warps, 2 CTAs/SM (split-K=4) ----
__global__ void __launch_bounds__(512, 2) gemm_v_mma()
{
    extern __shared__ float sm[];
    int t = threadIdx.x, wid = t >> 5, lane = t & 31;
    int z = blockIdx.x, rt = blockIdx.y;
    int mwarp = wid >> 2, nwarp = wid & 3;
    int mbase = mwarp * 32, nbase = nwarp * 32;
    int gr = lane >> 2, gc = lane & 3;
    const int NC = 16;

    int ft = t & 255;
    int fr = ft >> 1, fs = ft & 1;
    bool isB = t >= 256;
    const float* g0;
    if (!isB)
        g0 = g_Utf + (size_t)(rt * 128 + fr) * OMD + z * 512 + fs * 16;
    else
        g0 = g_BinjT + (size_t)fr * OMD + z * 512 + fs * 16;

    int ubase = (4 * fs) ^ (fr & 7);
    uint32_t d0 = smem_u32(sm + (isB ? 4096 : 0) + fr * 32 + ubase * 4);

    auto issue = [&](int jc) {
        const float* s = g0 + jc * 32;
        uint32_t da = d0 + (uint32_t)(jc % 3) * 32768u;
        #pragma unroll
        for (int i = 0; i < 4; i++) cp16(da ^ (i << 4), s + i * 4);
        asm volatile("cp.async.commit_group;" ::: "memory");
    };

    float acc[2][4][4] = {};
    int su = (2 * gc) ^ gr;

    issue(0); issue(1);
    for (int ic = 0; ic < NC; ic++) {
        if (ic + 2 < NC) { issue(ic + 2);
            asm volatile("cp.async.wait_group 2;" ::: "memory"); }
        else if (ic + 1 < NC)
            asm volatile("cp.async.wait_group 1;" ::: "memory");
        else
            asm volatile("cp.async.wait_group 0;" ::: "memory");
        __syncthreads();

        const float4* As4 = (const float4*)(sm + (ic % 3) * STG_F);
        const float4* Bs4 = As4 + 1024;
        #pragma unroll
        for (int h = 0; h < 2; h++) {
            int suh = su ^ h;
            float4 av[2][2], bv[4];
            #pragma unroll
            for (int mt = 0; mt < 2; mt++) {
                av[mt][0] = As4[(mbase + mt * 16 + gr) * 8 + suh];
                av[mt][1] = As4[(mbase + mt * 16 + 8 + gr) * 8 + suh];
            }
            #pragma unroll
            for (int nt = 0; nt < 4; nt++)
                bv[nt] = Bs4[(nbase + nt * 8 + gr) * 8 + suh];
            #pragma unroll
            for (int s2 = 0; s2 < 2; s2++) {
                #pragma unroll
                for (int mt = 0; mt < 2; mt++) {
                    const float* a0p = (const float*)&av[mt][0];
                    const float* a1p = (const float*)&av[mt][1];
                    #pragma unroll
                    for (int nt = 0; nt < 4; nt++) {
                        const float* bp = (const float*)&bv[nt];
                        mma8(acc[mt][nt], a0p[2*s2], a1p[2*s2],
                             a0p[2*s2+1], a1p[2*s2+1], bp[2*s2], bp[2*s2+1]);
                    }
                }
            }
        }
        __syncthreads();
    }

    float* Vp = g_Vpart + (size_t)z * NCH * NXD;
    #pragma unroll
    for (int mt = 0; mt < 2; mt++) {
        int rg0 = rt * 128 + mbase + mt * 16 + gr;
        int rg1 = rg0 + 8;
        #pragma unroll
        for (int nt = 0; nt < 4; nt++) {
            int col = nbase + nt * 8 + 2 * gc;
            float2 w0 = {acc[mt][nt][0], acc[mt][nt][1]};
            float2 w1 = {acc[mt][nt][2], acc[mt][nt][3]};
            *(float2*)(Vp + (size_t)rg0 * NXD + col) = w0;
            *(float2*)(Vp + (size_t)rg1 * NXD + col) = w1;
        }
    }
}

// ---------------- host launcher ---------------------------------------------
extern "C" void kernel_launch(void* const* d_in, const int* in_sizes, int n_in,
                              void* d_out, int out_size)
{
    const float* u   = (const float*)d_in[0];
    const float* M   = (const float*)d_in[1];
    const float* Bm  = (const float*)d_in[2];
    const float* C   = (const float*)d_in[3];
    const float* x0  = (const float*)d_in[4];
    float* out = (float*)d_out;

    float *pP, *pPtf, *pH, *pUtf;
    cudaGetSymbolAddress((void**)&pP, g_Pstack);
    cudaGetSymbolAddress((void**)&pPtf, g_Ptf);
    cudaGetSymbolAddress((void**)&pH, g_Hstack);
    cudaGetSymbolAddress((void**)&pUtf, g_Utf);

    cudaFuncSetAttribute(gemm_main_mma,
                         cudaFuncAttributeMaxDynamicSharedMemorySize, 98304);
    cudaFuncSetAttribute(gemm_v_mma,
                         cudaFuncAttributeMaxDynamicSharedMemorySize, 98304);
    cudaFuncSetAttribute(chunk_scan,
                         cudaFuncAttributeMaxDynamicSharedMemorySize, 66048);

    copy_bmat<<<32, 256>>>(Bm);                 // GB block 0
    copy_kernel<<<32, 256>>>(pP, C, 64 * 128);  // P block 0 = C
    ef_kernel<<<dim3(4, 4), dim3(32, 32)>>>(M);
    solve_kernel<<<1, 1024>>>();

    // 5 doubling steps: widths 64,128,256,512,1024 -> final 2048; A^32 = chain[5]
    for (int s = 0; s < 5; s++) {
        int w = 64 << s;
        fused_double<<<64 + w, dim3(16, 16)>>>(s);
    }

    // H = P @ B_mat (raw fp32 P, 2048 rows)
    mm_nn<<<dim3(4, 128), dim3(16, 16)>>>(pH, pP, Bm, OMD, 64, 128, 128, 64, 64);

    permute_tf32<<<(OMD * NXD) / 256, 256>>>(pPtf, pP, OMD * NXD);
    build_om<<<OMD, 256>>>();
    build_binjT<<<128, 256>>>();
    permute_tf32<<<(NB * TLEN * 64) / 256, 256>>>(pUtf, u, NB * TLEN * 64);

    gemm_v_mma<<<dim3(4, 32), 512, 98304>>>();
    reduce_v<<<2048, 256>>>();
    chunk_scan<<<32, 128, 66048>>>(x0);

    gemm_main_mma<<<dim3(16, 32), 512, 98304>>>(out);
}

// round 13
// speedup vs baseline: 1.5367x; 1.5367x over previous
#include <cuda_runtime.h>
#include <cstdint>
#include <cstddef>

#define NXD  128
#define TLEN 4096
#define NB   32
#define LCH  32
#define KCH  128
#define NCH  (NB*KCH)     // 4096 (batch, chunk) rows
#define OMD  2048         // LCH*64 : Omega dim, Y cols per (b,chunk) row
#define STG_F 8192        // floats per pipeline stage (A 4096 + B 4096)

// ---------------- static device workspaces ----------------------------------
__device__ float g_E[NXD*NXD];
__device__ float g_F[NXD*NXD];
__device__ float g_chain[7*NXD*NXD];          // A^(2^s), s=0..5 used
__device__ float g_Pstack[OMD*NXD];           // P_i = C A^i (raw fp32), 2048x128
__device__ float g_Ptf[OMD*NXD];              // P permuted + tf32
__device__ float g_GBwide[NXD*OMD];           // [A^m B] blocks (128 x 2048)
__device__ float g_BinjT[NXD*OMD];            // injection op^T, permuted+tf32
__device__ float g_Hstack[OMD*64];            // H_m = C A^m B (2048 x 64)
__device__ float g_Om[(size_t)OMD*OMD];       // Omega, permuted+tf32 (16MB)
__device__ float g_Utf[(size_t)NB*TLEN*64];   // U permuted + tf32 (32MB)
__device__ float g_V[NCH*NXD];
__device__ float g_Xp[NCH*NXD];               // chunk states, permuted+tf32
__device__ float g_Vpart[4*NCH*NXD];
__device__ unsigned long long g_fac[128*128]; // {fac:hi32, seq:lo32} per (k,row)

// ---------------- helpers ----------------------------------------------------
__device__ __forceinline__ float to_tf32(float x) {
    uint32_t u;
    asm("cvt.rna.tf32.f32 %0, %1;" : "=r"(u) : "f"(x));
    return __uint_as_float(u);
}
__device__ __forceinline__ uint32_t smem_u32(const void* p) {
    uint32_t a;
    asm("{ .reg .u64 t; cvta.to.shared.u64 t, %1; cvt.u32.u64 %0, t; }"
        : "=r"(a) : "l"(p));
    return a;
}
__device__ __forceinline__ void mma8(float* c, float a0, float a1, float a2,
                                     float a3, float b0, float b1) {
    asm volatile(
        "mma.sync.aligned.m16n8k8.row.col.f32.tf32.tf32.f32 "
        "{%0,%1,%2,%3}, {%4,%5,%6,%7}, {%8,%9}, {%0,%1,%2,%3};"
        : "+f"(c[0]), "+f"(c[1]), "+f"(c[2]), "+f"(c[3])
        : "r"(__float_as_uint(a0)), "r"(__float_as_uint(a1)),
          "r"(__float_as_uint(a2)), "r"(__float_as_uint(a3)),
          "r"(__float_as_uint(b0)), "r"(__float_as_uint(b1)));
}
__device__ __forceinline__ void cp16(uint32_t dst, const float* src) {
    asm volatile("cp.async.cg.shared.global [%0], [%1], 16;"
                 :: "r"(dst), "l"(src));
}
// permutation: source k (within 32-block) stored at pos (k%4)*8 + k/4
__device__ __forceinline__ int kperm(int j) { return ((j & 3) << 3) | (j >> 2); }

// ---------------- E, F from M ------------------------------------------------
__global__ void ef_kernel(const float* __restrict__ M)
{
    __shared__ float s0i[32][33], s1i[32][33], s0j[32][33], s1j[32][33];
    int tx = threadIdx.x, ty = threadIdx.y;
    int i0 = blockIdx.y * 32, j0 = blockIdx.x * 32;
    float e0 = 0.f, e1 = 0.f, f = 0.f;
    for (int kt = 0; kt < 256; kt += 32) {
        s0i[ty][tx] = M[(i0 + ty) * 256 + kt + tx];
        s1i[ty][tx] = M[(128 + i0 + ty) * 256 + kt + tx];
        s0j[ty][tx] = M[(j0 + ty) * 256 + kt + tx];
        s1j[ty][tx] = M[(128 + j0 + ty) * 256 + kt + tx];
        __syncthreads();
        #pragma unroll
        for (int kk = 0; kk < 32; kk++) {
            float a0 = s0i[ty][kk], a1 = s1i[ty][kk];
            float b0 = s0j[tx][kk], b1 = s1j[tx][kk];
            e0 += a0 * b0; e1 += a1 * b1; f += a1 * b0;
        }
        __syncthreads();
    }
    int i = i0 + ty, j = j0 + tx;
    float e = 0.5f * (e0 + e1);
    if (i == j) e += 1e-9f;
    g_E[i * NXD + j] = e;
    g_F[i * NXD + j] = f;
}

// ---------------- 2-CTA Gauss-Jordan: solve E A = F --------------------------
// CTA0 owns the E half (pivot columns) and publishes per-row factors to g_fac
// with release stores; CTA1 owns the F half, acquire-spins on g_fac, applies
// the same factors, and writes A to g_chain. CTA0 never waits on CTA1.
__global__ void __launch_bounds__(512) solve_kernel()
{
    __shared__ float4 prow4[2][32];      // this CTA's 128-col half of pivot row
    __shared__ float  sfac[2][128];      // CTA0 only: W[rq][k]
    int t = threadIdx.x;
    int cq = t >> 7, rq = t & 127;       // cq: 32-col group within the half

    bool isE = (blockIdx.x == 0);
    float4 w[8];
    {
        const float* src = (isE ? g_E : g_F) + rq * 128 + cq * 32;
        #pragma unroll
        for (int i = 0; i < 8; i++) w[i] = ((const float4*)src)[i];
    }

    if (isE) {
        for (int k = 0; k < 128; k++) {
            int b = k & 1;
            if (cq == (k >> 5)) {
                int jf4 = (k >> 2) & 7, jc = k & 3;
                float4 v = w[0];
                #pragma unroll
                for (int i = 1; i < 8; i++) if (jf4 == i) v = w[i];
                float f = (jc == 0) ? v.x : (jc == 1) ? v.y
                        : (jc == 2) ? v.z : v.w;
                sfac[b][rq] = f;
            }
            if (rq == k) {
                #pragma unroll
                for (int i = 0; i < 8; i++) prow4[b][cq * 8 + i] = w[i];
            }
            __syncthreads();

            float pv = sfac[b][k];
            float r;
            asm("rcp.approx.f32 %0, %1;" : "=f"(r) : "f"(pv));
            r = r * (2.0f - pv * r);
            r = r * (2.0f - pv * r);

            float facv;
            if (rq == k) {
                facv = r;
                #pragma unroll
                for (int i = 0; i < 8; i++) {
                    w[i].x *= r; w[i].y *= r; w[i].z *= r; w[i].w *= r;
                }
            } else {
                float factor = sfac[b][rq] * r;
                facv = factor;
                #pragma unroll
                for (int i = 0; i < 8; i++) {
                    float4 p = prow4[b][cq * 8 + i];
                    w[i].x -= factor * p.x; w[i].y -= factor * p.y;
                    w[i].z -= factor * p.z; w[i].w -= factor * p.w;
                }
            }
            if (cq == 0) {
                unsigned long long pk =
                    ((unsigned long long)__float_as_uint(facv) << 32)
                    | (unsigned)(k + 1);
                asm volatile("st.release.gpu.b64 [%0], %1;"
                             :: "l"(g_fac + k * 128 + rq), "l"(pk) : "memory");
            }
        }
        // E half is discarded
    } else {
        for (int k = 0; k < 128; k++) {
            int b = k & 1;
            if (rq == k) {
                #pragma unroll
                for (int i = 0; i < 8; i++) prow4[b][cq * 8 + i] = w[i];
            }
            __syncthreads();

            unsigned long long v;
            const unsigned long long* ptr = g_fac + k * 128 + rq;
            do {
                asm volatile("ld.acquire.gpu.b64 %0, [%1];"
                             : "=l"(v) : "l"(ptr) : "memory");
            } while ((unsigned)v != (unsigned)(k + 1));
            float fac = __uint_as_float((unsigned)(v >> 32));

            if (rq == k) {
                #pragma unroll
                for (int i = 0; i < 8; i++) {
                    w[i].x *= fac; w[i].y *= fac; w[i].z *= fac; w[i].w *= fac;
                }
            } else {
                #pragma unroll
                for (int i = 0; i < 8; i++) {
                    float4 p = prow4[b][cq * 8 + i];
                    w[i].x -= fac * p.x; w[i].y -= fac * p.y;
                    w[i].z -= fac * p.z; w[i].w -= fac * p.w;
                }
            }
        }
        float* dst = g_chain + rq * 128 + cq * 32;
        #pragma unroll
        for (int i = 0; i < 8; i++) ((float4*)dst)[i] = w[i];
    }
}

// ---------------- generic tiled GEMM C = A*B (row-major) for H ---------------
__global__ void mm_nn(float* __restrict__ Cc, const float* __restrict__ A,
                      const float* __restrict__ B,
                      int Mm, int Nn, int Kk, int lda, int ldb, int ldc)
{
    __shared__ float As[16][17], Bs[16][17];
    int tx = threadIdx.x, ty = threadIdx.y;
    int row = blockIdx.y * 16 + ty, col = blockIdx.x * 16 + tx;
    float acc = 0.f;
    for (int k0 = 0; k0 < Kk; k0 += 16) {
        As[ty][tx] = (row < Mm) ? A[row * lda + k0 + tx] : 0.f;
        Bs[ty][tx] = (col < Nn) ? B[(k0 + ty) * ldb + col] : 0.f;
        __syncthreads();
        #pragma unroll
        for (int kk = 0; kk < 16; kk++) acc += As[ty][kk] * Bs[kk][tx];
        __syncthreads();
    }
    if (row < Mm && col < Nn) Cc[row * ldc + col] = acc;
}

// ---------------- fused doubling step: chain^2, GB extend, P extend ----------
__global__ void fused_double(int s)
{
    int w = 64 << s;
    int t1 = w >> 1;
    int bid = blockIdx.x;
    const float* chain_s = g_chain + s * 16384;
    const float *Ain, *Bin; float* Cout;
    int bx, by, lda, ldb, ldc;
    if (bid < 64) {
        bx = bid & 7; by = bid >> 3;
        Ain = chain_s; Bin = chain_s; Cout = g_chain + (s + 1) * 16384;
        lda = 128; ldb = 128; ldc = 128;
    } else if (bid < 64 + t1) {
        int r = bid - 64; int nt = w >> 4;
        bx = r % nt; by = r / nt;
        Ain = chain_s; Bin = g_GBwide; Cout = g_GBwide + w;
        lda = 128; ldb = OMD; ldc = OMD;
    } else {
        int r = bid - 64 - t1;
        bx = r & 7; by = r >> 3;
        Ain = g_Pstack; Bin = chain_s; Cout = g_Pstack + w * 128;
        lda = 128; ldb = 128; ldc = 128;
    }
    __shared__ float As[16][17], Bs[16][17];
    int tx = threadIdx.x, ty = threadIdx.y;
    int row = by * 16 + ty, col = bx * 16 + tx;
    float acc = 0.f;
    for (int k0 = 0; k0 < 128; k0 += 16) {
        As[ty][tx] = Ain[row * lda + k0 + tx];
        Bs[ty][tx] = Bin[(k0 + ty) * ldb + col];
        __syncthreads();
        #pragma unroll
        for (int kk = 0; kk < 16; kk++) acc += As[ty][kk] * Bs[kk][tx];
        __syncthreads();
    }
    Cout[row * ldc + col] = acc;
}

// ---------------- small helpers ---------------------------------------------
__global__ void copy_kernel(float* __restrict__ dst, const float* __restrict__ src, int n)
{
    int i = blockIdx.x * blockDim.x + threadIdx.x;
    if (i < n) dst[i] = src[i];
}

__global__ void copy_bmat(const float* __restrict__ Bm)
{
    int i = blockIdx.x * blockDim.x + threadIdx.x;
    if (i < 128 * 64) {
        int r = i >> 6, c = i & 63;
        g_GBwide[r * OMD + c] = Bm[i];
    }
}

// permute within 32-float blocks + tf32 round
__global__ void permute_tf32(float* __restrict__ dst, const float* __restrict__ src,
                             int n)
{
    int i = blockIdx.x * blockDim.x + threadIdx.x;
    if (i >= n) return;
    int q = i & 31;
    int j = ((q & 7) << 2) | (q >> 3);       // inverse permutation
    dst[i] = to_tf32(src[(i - q) + j]);
}

// BinjT[n][perm(q)] = tf32( (A^(31-j) B)[n][uu] ),  q = j*64+uu
__global__ void build_binjT()
{
    int n = blockIdx.x;
    for (int q = threadIdx.x; q < OMD; q += blockDim.x) {
        float v = g_GBwide[n * OMD + (31 - (q >> 6)) * 64 + (q & 63)];
        g_BinjT[n * OMD + (q & ~31) + kperm(q & 31)] = to_tf32(v);
    }
}

// Om[p][perm(q)] = (j<i) ? tf32(H_{i-1-j}[o][uu]) : 0   p=(i,o), i,j 0..31
__global__ void build_om()
{
    int p = blockIdx.x;
    int i = p >> 6, o = p & 63;
    size_t base = (size_t)p * OMD;
    for (int q = threadIdx.x; q < OMD; q += blockDim.x) {
        int j = q >> 6, uu = q & 63;
        float v = 0.f;
        if (j < i) v = to_tf32(g_Hstack[(((i - 1 - j) << 6) + o) * 64 + uu]);
        g_Om[base + (q & ~31) + kperm(q & 31)] = v;
    }
}

__global__ void reduce_v()
{
    int i = blockIdx.x * blockDim.x + threadIdx.x;
    if (i < NCH * NXD) {
        float s = 0.f;
        #pragma unroll
        for (int z = 0; z < 4; z++) s += g_Vpart[(size_t)z * NCH * NXD + i];
        g_V[i] = s;
    }
}

// ---------------- chunk-level scan (A^32, 127 steps) -------------------------
__global__ void __launch_bounds__(128) chunk_scan(const float* __restrict__ x0)
{
    extern __shared__ float At[];        // 128*129 floats
    __shared__ float xs[128];
    int b = blockIdx.x, n = threadIdx.x;
    int np = (n & ~31) | kperm(n & 31);
    const float* A32 = g_chain + 5 * NXD * NXD;
    for (int idx = n; idx < 128 * 128; idx += 128) {
        int row = idx >> 7, col = idx & 127;
        At[col * 129 + row] = A32[idx];
    }
    xs[n] = x0[n];
    __syncthreads();
    g_Xp[(b * KCH + 0) * NXD + np] = to_tf32(xs[n]);
    for (int k = 0; k < KCH - 1; k++) {
        float acc = g_V[(b * KCH + k) * NXD + n];
        #pragma unroll 8
        for (int m = 0; m < 128; m++) acc += At[m * 129 + n] * xs[m];
        __syncthreads();
        xs[n] = acc;
        __syncthreads();
        g_Xp[(b * KCH + k + 1) * NXD + np] = to_tf32(acc);
    }
}

// ---------------- main GEMM via mma.sync tf32, 16 warps ----------------------
// Y(4096 x 2048) = Uc * Om^T (triangular cutoff) + X * P^T
// CTA 128x128, 16 warps (4x4), warp tile 32x32, BK=32, 3-stage cp.async.
__global__ void __launch_bounds__(512) gemm_main_mma(float* __restrict__ out)
{
    extern __shared__ float sm[];
    int t = threadIdx.x, wid = t >> 5, lane = t & 31;
    int ct = 15 - blockIdx.x, rt = blockIdx.y;
    int mwarp = wid >> 2, nwarp = wid & 3;
    int mbase = mwarp * 32, nbase = nwarp * 32;
    int gr = lane >> 2, gc = lane & 3;

    int kend = (2 * ct + 1) * 64;
    int nU = kend >> 5;
    int NC = nU + 4;

    int ft = t & 255;
    int fr = ft >> 1, fs = ft & 1;
    bool isB = t >= 256;
    const float* g0;
    const float* g1;
    if (!isB) {
        g0 = g_Utf + (size_t)(rt * 128 + fr) * OMD + fs * 16;
        g1 = g_Xp  + (rt * 128 + fr) * NXD + fs * 16;
    } else {
        g0 = g_Om  + (size_t)(ct * 128 + fr) * OMD + fs * 16;
        g1 = g_Ptf + (ct * 128 + fr) * NXD + fs * 16;
    }

    int ubase = (4 * fs) ^ (fr & 7);
    uint32_t d0 = smem_u32(sm + (isB ? 4096 : 0) + fr * 32 + ubase * 4);

    auto issue = [&](int jc) {
        const float* s = (jc < nU) ? (g0 + jc * 32) : (g1 + (jc - nU) * 32);
        uint32_t da = d0 + (uint32_t)(jc % 3) * 32768u;
        #pragma unroll
        for (int i = 0; i < 4; i++) cp16(da ^ (i << 4), s + i * 4);
        asm volatile("cp.async.commit_group;" ::: "memory");
    };

    float acc[2][4][4] = {};
    int su = (2 * gc) ^ gr;

    issue(0);
    if (NC > 1) issue(1);

    for (int ic = 0; ic < NC; ic++) {
        if (ic + 2 < NC) { issue(ic + 2);
            asm volatile("cp.async.wait_group 2;" ::: "memory"); }
        else if (ic + 1 < NC)
            asm volatile("cp.async.wait_group 1;" ::: "memory");
        else
            asm volatile("cp.async.wait_group 0;" ::: "memory");
        __syncthreads();

        const float4* As4 = (const float4*)(sm + (ic % 3) * STG_F);
        const float4* Bs4 = As4 + 1024;
        #pragma unroll
        for (int h = 0; h < 2; h++) {
            int suh = su ^ h;
            float4 av[2][2], bv[4];
            #pragma unroll
            for (int mt = 0; mt < 2; mt++) {
                av[mt][0] = As4[(mbase + mt * 16 + gr) * 8 + suh];
                av[mt][1] = As4[(mbase + mt * 16 + 8 + gr) * 8 + suh];
            }
            #pragma unroll
            for (int nt = 0; nt < 4; nt++)
                bv[nt] = Bs4[(nbase + nt * 8 + gr) * 8 + suh];
            #pragma unroll
            for (int s2 = 0; s2 < 2; s2++) {
                #pragma unroll
                for (int mt = 0; mt < 2; mt++) {
                    const float* a0p = (const float*)&av[mt][0];
                    const float* a1p = (const float*)&av[mt][1];
                    #pragma unroll
                    for (int nt = 0; nt < 4; nt++) {
                        const float* bp = (const float*)&bv[nt];
                        mma8(acc[mt][nt], a0p[2*s2], a1p[2*s2],
                             a0p[2*s2+1], a1p[2*s2+1], bp[2*s2], bp[2*s2+1]);
                    }
                }
            }
        }
        __syncthreads();
    }

    // epilogue: out rows are contiguous 2048-float spans
    #pragma unroll
    for (int mt = 0; mt < 2; mt++) {
        int rg0 = rt * 128 + mbase + mt * 16 + gr;
        int rg1 = rg0 + 8;
        float* base0 = out + (size_t)rg0 * OMD;
        float* base1 = out + (size_t)rg1 * OMD;
        #pragma unroll
        for (int nt = 0; nt < 4; nt++) {
            int p = ct * 128 + nbase + nt * 8 + 2 * gc;
            float2 w0 = {acc[mt][nt][0], acc[mt][nt][1]};
            float2 w1 = {acc[mt][nt][2], acc[mt][nt][3]};
            *(float2*)(base0 + p) = w0;
            *(float2*)(base1 + p) = w1;
        }
    }
}

// ---------------- injection GEMM via mma, 16 warps (split-K=4) ---------------
__global__ void __launch_bounds__(512) gemm_v_mma()
{
    extern __shared__ float sm[];
    int t = threadIdx.x, wid = t >> 5, lane = t & 31;
    int z = blockIdx.x, rt = blockIdx.y;
    int mwarp = wid >> 2, nwarp = wid & 3;
    int mbase = mwarp * 32, nbase = nwarp * 32;
    int gr = lane >> 2, gc = lane & 3;
    const int NC = 16;

    int ft = t & 255;
    int fr = ft >> 1, fs = ft & 1;
    bool isB = t >= 256;
    const float* g0;
    if (!isB)
        g0 = g_Utf + (size_t)(rt * 128 + fr) * OMD + z * 512 + fs * 16;
    else
        g0 = g_BinjT + (size_t)fr * OMD + z * 512 + fs * 16;

    int ubase = (4 * fs) ^ (fr & 7);
    uint32_t d0 = smem_u32(sm + (isB ? 4096 : 0) + fr * 32 + ubase * 4);

    auto issue = [&](int jc) {
        const float* s = g0 + jc * 32;
        uint32_t da = d0 + (uint32_t)(jc % 3) * 32768u;
        #pragma unroll
        for (int i = 0; i < 4; i++) cp16(da ^ (i << 4), s + i * 4);
        asm volatile("cp.async.commit_group;" ::: "memory");
    };

    float acc[2][4][4] = {};
    int su = (2 * gc) ^ gr;

    issue(0); issue(1);
    for (int ic = 0; ic < NC; ic++) {
        if (ic + 2 < NC) { issue(ic + 2);
            asm volatile("cp.async.wait_group 2;" ::: "memory"); }
        else if (ic + 1 < NC)
            asm volatile("cp.async.wait_group 1;" ::: "memory");
        else
            asm volatile("cp.async.wait_group 0;" ::: "memory");
        __syncthreads();

        const float4* As4 = (const float4*)(sm + (ic % 3) * STG_F);
        const float4* Bs4 = As4 + 1024;
        #pragma unroll
        for (int h = 0; h < 2; h++) {
            int suh = su ^ h;
            float4 av[2][2], bv[4];
            #pragma unroll
            for (int mt = 0; mt < 2; mt++) {
                av[mt][0] = As4[(mbase + mt * 16 + gr) * 8 + suh];
                av[mt][1] = As4[(mbase + mt * 16 + 8 + gr) * 8 + suh];
            }
            #pragma unroll
            for (int nt = 0; nt < 4; nt++)
                bv[nt] = Bs4[(nbase + nt * 8 + gr) * 8 + suh];
            #pragma unroll
            for (int s2 = 0; s2 < 2; s2++) {
                #pragma unroll
                for (int mt = 0; mt < 2; mt++) {
                    const float* a0p = (const float*)&av[mt][0];
                    const float* a1p = (const float*)&av[mt][1];
                    #pragma unroll
                    for (int nt = 0; nt < 4; nt++) {
                        const float* bp = (const float*)&bv[nt];
                        mma8(acc[mt][nt], a0p[2*s2], a1p[2*s2],
                             a0p[2*s2+1], a1p[2*s2+1], bp[2*s2], bp[2*s2+1]);
                    }
                }
            }
        }
        __syncthreads();
    }

    float* Vp = g_Vpart + (size_t)z * NCH * NXD;
    #pragma unroll
    for (int mt = 0; mt < 2; mt++) {
        int rg0 = rt * 128 + mbase + mt * 16 + gr;
        int rg1 = rg0 + 8;
        #pragma unroll
        for (int nt = 0; nt < 4; nt++) {
            int col = nbase + nt * 8 + 2 * gc;
            float2 w0 = {acc[mt][nt][0], acc[mt][nt][1]};
            float2 w1 = {acc[mt][nt][2], acc[mt][nt][3]};
            *(float2*)(Vp + (size_t)rg0 * NXD + col) = w0;
            *(float2*)(Vp + (size_t)rg1 * NXD + col) = w1;
        }
    }
}

// ---------------- host launcher ---------------------------------------------
extern "C" void kernel_launch(void* const* d_in, const int* in_sizes, int n_in,
                              void* d_out, int out_size)
{
    const float* u   = (const float*)d_in[0];
    const float* M   = (const float*)d_in[1];
    const float* Bm  = (const float*)d_in[2];
    const float* C   = (const float*)d_in[3];
    const float* x0  = (const float*)d_in[4];
    float* out = (float*)d_out;

    float *pP, *pPtf, *pH, *pUtf;
    cudaGetSymbolAddress((void**)&pP, g_Pstack);
    cudaGetSymbolAddress((void**)&pPtf, g_Ptf);
    cudaGetSymbolAddress((void**)&pH, g_Hstack);
    cudaGetSymbolAddress((void**)&pUtf, g_Utf);

    cudaFuncSetAttribute(gemm_main_mma,
                         cudaFuncAttributeMaxDynamicSharedMemorySize, 98304);
    cudaFuncSetAttribute(gemm_v_mma,
                         cudaFuncAttributeMaxDynamicSharedMemorySize, 98304);
    cudaFuncSetAttribute(chunk_scan,
                         cudaFuncAttributeMaxDynamicSharedMemorySize, 66048);

    copy_bmat<<<32, 256>>>(Bm);                 // GB block 0
    copy_kernel<<<32, 256>>>(pP, C, 64 * 128);  // P block 0 = C
    ef_kernel<<<dim3(4, 4), dim3(32, 32)>>>(M);
    solve_kernel<<<2, 512>>>();

    // 5 doubling steps: widths 64,128,256,512,1024 -> final 2048; A^32 = chain[5]
    for (int s = 0; s < 5; s++) {
        int w = 64 << s;
        fused_double<<<64 + w, dim3(16, 16)>>>(s);
    }

    // H = P @ B_mat (raw fp32 P, 2048 rows)
    mm_nn<<<dim3(4, 128), dim3(16, 16)>>>(pH, pP, Bm, OMD, 64, 128, 128, 64, 64);

    permute_tf32<<<(OMD * NXD) / 256, 256>>>(pPtf, pP, OMD * NXD);
    build_om<<<OMD, 256>>>();
    build_binjT<<<128, 256>>>();
    permute_tf32<<<(NB * TLEN * 64) / 256, 256>>>(pUtf, u, NB * TLEN * 64);

    gemm_v_mma<<<dim3(4, 32), 512, 98304>>>();
    reduce_v<<<2048, 256>>>();
    chunk_scan<<<32, 128, 66048>>>(x0);

    gemm_main_mma<<<dim3(16, 32), 512, 98304>>>(out);
}

// round 14
// speedup vs baseline: 1.5675x; 1.0200x over previous
#include <cuda_runtime.h>
#include <cstdint>
#include <cstddef>

#define NXD  128
#define TLEN 4096
#define NB   32
#define LCH  32
#define KCH  128
#define NCH  (NB*KCH)     // 4096 (batch, chunk) rows
#define OMD  2048         // LCH*64 : Omega dim, Y cols per (b,chunk) row
#define STG_F 8192        // floats per pipeline stage (A 4096 + B 4096)

// ---------------- static device workspaces ----------------------------------
__device__ float g_E[NXD*NXD];
__device__ float g_F[NXD*NXD];
__device__ float g_chain[7*NXD*NXD];          // A^(2^s), s=0..5 used
__device__ float g_Pstack[OMD*NXD];           // P_i = C A^i (raw fp32), 2048x128
__device__ float g_Ptf[OMD*NXD];              // P permuted + tf32
__device__ float g_GBwide[NXD*OMD];           // [A^m B] blocks (128 x 2048)
__device__ float g_BinjT[NXD*OMD];            // injection op^T, permuted+tf32
__device__ float g_Hstack[OMD*64];            // H_m = C A^m B (2048 x 64)
__device__ float g_Om[(size_t)OMD*OMD];       // Omega, permuted+tf32 (16MB)
__device__ float g_Utf[(size_t)NB*TLEN*64];   // U permuted + tf32 (32MB)
__device__ float g_V[NCH*NXD];
__device__ float g_Xp[NCH*NXD];               // chunk states, permuted+tf32
__device__ float g_Vpart[4*NCH*NXD];
__device__ unsigned long long g_fac[128*128]; // {fac:hi32, seq:lo32} per (k,row)

// ---------------- helpers ----------------------------------------------------
__device__ __forceinline__ float to_tf32(float x) {
    uint32_t u;
    asm("cvt.rna.tf32.f32 %0, %1;" : "=r"(u) : "f"(x));
    return __uint_as_float(u);
}
__device__ __forceinline__ uint32_t smem_u32(const void* p) {
    uint32_t a;
    asm("{ .reg .u64 t; cvta.to.shared.u64 t, %1; cvt.u32.u64 %0, t; }"
        : "=r"(a) : "l"(p));
    return a;
}
__device__ __forceinline__ void mma8(float* c, float a0, float a1, float a2,
                                     float a3, float b0, float b1) {
    asm volatile(
        "mma.sync.aligned.m16n8k8.row.col.f32.tf32.tf32.f32 "
        "{%0,%1,%2,%3}, {%4,%5,%6,%7}, {%8,%9}, {%0,%1,%2,%3};"
        : "+f"(c[0]), "+f"(c[1]), "+f"(c[2]), "+f"(c[3])
        : "r"(__float_as_uint(a0)), "r"(__float_as_uint(a1)),
          "r"(__float_as_uint(a2)), "r"(__float_as_uint(a3)),
          "r"(__float_as_uint(b0)), "r"(__float_as_uint(b1)));
}
__device__ __forceinline__ void cp16(uint32_t dst, const float* src) {
    asm volatile("cp.async.cg.shared.global [%0], [%1], 16;"
                 :: "r"(dst), "l"(src));
}
// permutation: source k (within 32-block) stored at pos (k%4)*8 + k/4
__device__ __forceinline__ int kperm(int j) { return ((j & 3) << 3) | (j >> 2); }

// ---------------- E, F from M ------------------------------------------------
__global__ void ef_kernel(const float* __restrict__ M)
{
    __shared__ float s0i[32][33], s1i[32][33], s0j[32][33], s1j[32][33];
    int tx = threadIdx.x, ty = threadIdx.y;
    int i0 = blockIdx.y * 32, j0 = blockIdx.x * 32;
    float e0 = 0.f, e1 = 0.f, f = 0.f;
    for (int kt = 0; kt < 256; kt += 32) {
        s0i[ty][tx] = M[(i0 + ty) * 256 + kt + tx];
        s1i[ty][tx] = M[(128 + i0 + ty) * 256 + kt + tx];
        s0j[ty][tx] = M[(j0 + ty) * 256 + kt + tx];
        s1j[ty][tx] = M[(128 + j0 + ty) * 256 + kt + tx];
        __syncthreads();
        #pragma unroll
        for (int kk = 0; kk < 32; kk++) {
            float a0 = s0i[ty][kk], a1 = s1i[ty][kk];
            float b0 = s0j[tx][kk], b1 = s1j[tx][kk];
            e0 += a0 * b0; e1 += a1 * b1; f += a1 * b0;
        }
        __syncthreads();
    }
    int i = i0 + ty, j = j0 + tx;
    float e = 0.5f * (e0 + e1);
    if (i == j) e += 1e-9f;
    g_E[i * NXD + j] = e;
    g_F[i * NXD + j] = f;
}

// ---------------- 2-CTA Gauss-Jordan: solve E A = F (R13 proven) -------------
__global__ void __launch_bounds__(512) solve_kernel()
{
    __shared__ float4 prow4[2][32];
    __shared__ float  sfac[2][128];
    int t = threadIdx.x;
    int cq = t >> 7, rq = t & 127;

    bool isE = (blockIdx.x == 0);
    float4 w[8];
    {
        const float* src = (isE ? g_E : g_F) + rq * 128 + cq * 32;
        #pragma unroll
        for (int i = 0; i < 8; i++) w[i] = ((const float4*)src)[i];
    }

    if (isE) {
        for (int k = 0; k < 128; k++) {
            int b = k & 1;
            if (cq == (k >> 5)) {
                int jf4 = (k >> 2) & 7, jc = k & 3;
                float4 v = w[0];
                #pragma unroll
                for (int i = 1; i < 8; i++) if (jf4 == i) v = w[i];
                float f = (jc == 0) ? v.x : (jc == 1) ? v.y
                        : (jc == 2) ? v.z : v.w;
                sfac[b][rq] = f;
            }
            if (rq == k) {
                #pragma unroll
                for (int i = 0; i < 8; i++) prow4[b][cq * 8 + i] = w[i];
            }
            __syncthreads();

            float pv = sfac[b][k];
            float r;
            asm("rcp.approx.f32 %0, %1;" : "=f"(r) : "f"(pv));
            r = r * (2.0f - pv * r);
            r = r * (2.0f - pv * r);

            float facv;
            if (rq == k) {
                facv = r;
                #pragma unroll
                for (int i = 0; i < 8; i++) {
                    w[i].x *= r; w[i].y *= r; w[i].z *= r; w[i].w *= r;
                }
            } else {
                float factor = sfac[b][rq] * r;
                facv = factor;
                #pragma unroll
                for (int i = 0; i < 8; i++) {
                    float4 p = prow4[b][cq * 8 + i];
                    w[i].x -= factor * p.x; w[i].y -= factor * p.y;
                    w[i].z -= factor * p.z; w[i].w -= factor * p.w;
                }
            }
            if (cq == 0) {
                unsigned long long pk =
                    ((unsigned long long)__float_as_uint(facv) << 32)
                    | (unsigned)(k + 1);
                asm volatile("st.release.gpu.b64 [%0], %1;"
                             :: "l"(g_fac + k * 128 + rq), "l"(pk) : "memory");
            }
        }
    } else {
        for (int k = 0; k < 128; k++) {
            int b = k & 1;
            if (rq == k) {
                #pragma unroll
                for (int i = 0; i < 8; i++) prow4[b][cq * 8 + i] = w[i];
            }
            __syncthreads();

            unsigned long long v;
            const unsigned long long* ptr = g_fac + k * 128 + rq;
            do {
                asm volatile("ld.acquire.gpu.b64 %0, [%1];"
                             : "=l"(v) : "l"(ptr) : "memory");
            } while ((unsigned)v != (unsigned)(k + 1));
            float fac = __uint_as_float((unsigned)(v >> 32));

            if (rq == k) {
                #pragma unroll
                for (int i = 0; i < 8; i++) {
                    w[i].x *= fac; w[i].y *= fac; w[i].z *= fac; w[i].w *= fac;
                }
            } else {
                #pragma unroll
                for (int i = 0; i < 8; i++) {
                    float4 p = prow4[b][cq * 8 + i];
                    w[i].x -= fac * p.x; w[i].y -= fac * p.y;
                    w[i].z -= fac * p.z; w[i].w -= fac * p.w;
                }
            }
        }
        float* dst = g_chain + rq * 128 + cq * 32;
        #pragma unroll
        for (int i = 0; i < 8; i++) ((float4*)dst)[i] = w[i];
    }
}

// ---------------- generic tiled GEMM C = A*B (row-major) for H ---------------
__global__ void mm_nn(float* __restrict__ Cc, const float* __restrict__ A,
                      const float* __restrict__ B,
                      int Mm, int Nn, int Kk, int lda, int ldb, int ldc)
{
    __shared__ float As[16][17], Bs[16][17];
    int tx = threadIdx.x, ty = threadIdx.y;
    int row = blockIdx.y * 16 + ty, col = blockIdx.x * 16 + tx;
    float acc = 0.f;
    for (int k0 = 0; k0 < Kk; k0 += 16) {
        As[ty][tx] = (row < Mm) ? A[row * lda + k0 + tx] : 0.f;
        Bs[ty][tx] = (col < Nn) ? B[(k0 + ty) * ldb + col] : 0.f;
        __syncthreads();
        #pragma unroll
        for (int kk = 0; kk < 16; kk++) acc += As[ty][kk] * Bs[kk][tx];
        __syncthreads();
    }
    if (row < Mm && col < Nn) Cc[row * ldc + col] = acc;
}

// ---------------- fused doubling step: chain^2, GB extend, P extend ----------
__global__ void fused_double(int s)
{
    int w = 64 << s;
    int t1 = w >> 1;
    int bid = blockIdx.x;
    const float* chain_s = g_chain + s * 16384;
    const float *Ain, *Bin; float* Cout;
    int bx, by, lda, ldb, ldc;
    if (bid < 64) {
        bx = bid & 7; by = bid >> 3;
        Ain = chain_s; Bin = chain_s; Cout = g_chain + (s + 1) * 16384;
        lda = 128; ldb = 128; ldc = 128;
    } else if (bid < 64 + t1) {
        int r = bid - 64; int nt = w >> 4;
        bx = r % nt; by = r / nt;
        Ain = chain_s; Bin = g_GBwide; Cout = g_GBwide + w;
        lda = 128; ldb = OMD; ldc = OMD;
    } else {
        int r = bid - 64 - t1;
        bx = r & 7; by = r >> 3;
        Ain = g_Pstack; Bin = chain_s; Cout = g_Pstack + w * 128;
        lda = 128; ldb = 128; ldc = 128;
    }
    __shared__ float As[16][17], Bs[16][17];
    int tx = threadIdx.x, ty = threadIdx.y;
    int row = by * 16 + ty, col = bx * 16 + tx;
    float acc = 0.f;
    for (int k0 = 0; k0 < 128; k0 += 16) {
        As[ty][tx] = Ain[row * lda + k0 + tx];
        Bs[ty][tx] = Bin[(k0 + ty) * ldb + col];
        __syncthreads();
        #pragma unroll
        for (int kk = 0; kk < 16; kk++) acc += As[ty][kk] * Bs[kk][tx];
        __syncthreads();
    }
    Cout[row * ldc + col] = acc;
}

// ---------------- small helpers ---------------------------------------------
__global__ void copy_kernel(float* __restrict__ dst, const float* __restrict__ src, int n)
{
    int i = blockIdx.x * blockDim.x + threadIdx.x;
    if (i < n) dst[i] = src[i];
}

__global__ void copy_bmat(const float* __restrict__ Bm)
{
    int i = blockIdx.x * blockDim.x + threadIdx.x;
    if (i < 128 * 64) {
        int r = i >> 6, c = i & 63;
        g_GBwide[r * OMD + c] = Bm[i];
    }
}

// permute within 32-float blocks + tf32 round
__global__ void permute_tf32(float* __restrict__ dst, const float* __restrict__ src,
                             int n)
{
    int i = blockIdx.x * blockDim.x + threadIdx.x;
    if (i >= n) return;
    int q = i & 31;
    int j = ((q & 7) << 2) | (q >> 3);       // inverse permutation
    dst[i] = to_tf32(src[(i - q) + j]);
}

// BinjT[n][perm(q)] = tf32( (A^(31-j) B)[n][uu] ),  q = j*64+uu
__global__ void build_binjT()
{
    int n = blockIdx.x;
    for (int q = threadIdx.x; q < OMD; q += blockDim.x) {
        float v = g_GBwide[n * OMD + (31 - (q >> 6)) * 64 + (q & 63)];
        g_BinjT[n * OMD + (q & ~31) + kperm(q & 31)] = to_tf32(v);
    }
}

// Om[p][perm(q)] = (j<i) ? tf32(H_{i-1-j}[o][uu]) : 0   p=(i,o), i,j 0..31
__global__ void build_om()
{
    int p = blockIdx.x;
    int i = p >> 6, o = p & 63;
    size_t base = (size_t)p * OMD;
    for (int q = threadIdx.x; q < OMD; q += blockDim.x) {
        int j = q >> 6, uu = q & 63;
        float v = 0.f;
        if (j < i) v = to_tf32(g_Hstack[(((i - 1 - j) << 6) + o) * 64 + uu]);
        g_Om[base + (q & ~31) + kperm(q & 31)] = v;
    }
}

__global__ void reduce_v()
{
    int i = blockIdx.x * blockDim.x + threadIdx.x;
    if (i < NCH * NXD) {
        float s = 0.f;
        #pragma unroll
        for (int z = 0; z < 4; z++) s += g_Vpart[(size_t)z * NCH * NXD + i];
        g_V[i] = s;
    }
}

// ---------------- chunk-level scan (A^32, 127 steps) -------------------------
__global__ void __launch_bounds__(128) chunk_scan(const float* __restrict__ x0)
{
    extern __shared__ float At[];        // 128*129 floats
    __shared__ float xs[128];
    int b = blockIdx.x, n = threadIdx.x;
    int np = (n & ~31) | kperm(n & 31);
    const float* A32 = g_chain + 5 * NXD * NXD;
    for (int idx = n; idx < 128 * 128; idx += 128) {
        int row = idx >> 7, col = idx & 127;
        At[col * 129 + row] = A32[idx];
    }
    xs[n] = x0[n];
    __syncthreads();
    g_Xp[(b * KCH + 0) * NXD + np] = to_tf32(xs[n]);
    for (int k = 0; k < KCH - 1; k++) {
        float acc = g_V[(b * KCH + k) * NXD + n];
        #pragma unroll 8
        for (int m = 0; m < 128; m++) acc += At[m * 129 + n] * xs[m];
        __syncthreads();
        xs[n] = acc;
        __syncthreads();
        g_Xp[(b * KCH + k + 1) * NXD + np] = to_tf32(acc);
    }
}

// ---------------- main GEMM: 256 threads / 8 warps, 2 CTAs per SM ------------
// Y(4096 x 2048) = Uc * Om^T (triangular cutoff) + X * P^T
// CTA 128x128, 8 warps (2x4), warp tile 64x32, BK=32, 3-stage cp.async.
// Two independent CTAs per SM fill each other's barrier bubbles.
__global__ void __launch_bounds__(256, 2) gemm_main_mma(float* __restrict__ out)
{
    extern __shared__ float sm[];
    int t = threadIdx.x, wid = t >> 5, lane = t & 31;
    int ct = 15 - blockIdx.x, rt = blockIdx.y;
    int mwarp = wid >> 2, nwarp = wid & 3;
    int mbase = mwarp * 64, nbase = nwarp * 32;
    int gr = lane >> 2, gc = lane & 3;

    int kend = (2 * ct + 1) * 64;
    int nU = kend >> 5;
    int NC = nU + 4;

    int fr = t >> 1, fs = t & 1;
    const float* AgU = g_Utf + (size_t)(rt * 128 + fr) * OMD + fs * 16;
    const float* BgO = g_Om  + (size_t)(ct * 128 + fr) * OMD + fs * 16;
    const float* AgX = g_Xp  + (rt * 128 + fr) * NXD + fs * 16;
    const float* BgP = g_Ptf + (ct * 128 + fr) * NXD + fs * 16;

    int ubase = (4 * fs) ^ (fr & 7);
    uint32_t dA0 = smem_u32(sm + fr * 32 + ubase * 4);
    uint32_t dB0 = dA0 + 16384;

    auto issue = [&](int jc) {
        const float *sa, *sb;
        if (jc < nU) { sa = AgU + jc * 32; sb = BgO + jc * 32; }
        else { int ko = (jc - nU) * 32; sa = AgX + ko; sb = BgP + ko; }
        uint32_t off = (uint32_t)(jc % 3) * 32768u;
        uint32_t da = dA0 + off, db = dB0 + off;
        #pragma unroll
        for (int i = 0; i < 4; i++) {
            cp16(da ^ (i << 4), sa + i * 4);
            cp16(db ^ (i << 4), sb + i * 4);
        }
        asm volatile("cp.async.commit_group;" ::: "memory");
    };

    float acc[4][4][4] = {};
    int su = (2 * gc) ^ gr;

    issue(0);
    if (NC > 1) issue(1);

    for (int ic = 0; ic < NC; ic++) {
        if (ic + 2 < NC) { issue(ic + 2);
            asm volatile("cp.async.wait_group 2;" ::: "memory"); }
        else if (ic + 1 < NC)
            asm volatile("cp.async.wait_group 1;" ::: "memory");
        else
            asm volatile("cp.async.wait_group 0;" ::: "memory");
        __syncthreads();

        const float4* As4 = (const float4*)(sm + (ic % 3) * STG_F);
        const float4* Bs4 = As4 + 1024;
        #pragma unroll
        for (int h = 0; h < 2; h++) {
            int suh = su ^ h;
            float4 av[4][2], bv[4];
            #pragma unroll
            for (int mt = 0; mt < 4; mt++) {
                av[mt][0] = As4[(mbase + mt * 16 + gr) * 8 + suh];
                av[mt][1] = As4[(mbase + mt * 16 + 8 + gr) * 8 + suh];
            }
            #pragma unroll
            for (int nt = 0; nt < 4; nt++)
                bv[nt] = Bs4[(nbase + nt * 8 + gr) * 8 + suh];
            #pragma unroll
            for (int s2 = 0; s2 < 2; s2++) {
                #pragma unroll
                for (int mt = 0; mt < 4; mt++) {
                    const float* a0p = (const float*)&av[mt][0];
                    const float* a1p = (const float*)&av[mt][1];
                    #pragma unroll
                    for (int nt = 0; nt < 4; nt++) {
                        const float* bp = (const float*)&bv[nt];
                        mma8(acc[mt][nt], a0p[2*s2], a1p[2*s2],
                             a0p[2*s2+1], a1p[2*s2+1], bp[2*s2], bp[2*s2+1]);
                    }
                }
            }
        }
        __syncthreads();
    }

    // epilogue: out rows are contiguous 2048-float spans
    #pragma unroll
    for (int mt = 0; mt < 4; mt++) {
        int rg0 = rt * 128 + mbase + mt * 16 + gr;
        int rg1 = rg0 + 8;
        float* base0 = out + (size_t)rg0 * OMD;
        float* base1 = out + (size_t)rg1 * OMD;
        #pragma unroll
        for (int nt = 0; nt < 4; nt++) {
            int p = ct * 128 + nbase + nt * 8 + 2 * gc;
            float2 w0 = {acc[mt][nt][0], acc[mt][nt][1]};
            float2 w1 = {acc[mt][nt][2], acc[mt][nt][3]};
            *(float2*)(base0 + p) = w0;
            *(float2*)(base1 + p) = w1;
        }
    }
}

// ---------------- injection GEMM: 256 threads / 8 warps, 2 CTAs/SM -----------
__global__ void __launch_bounds__(256, 2) gemm_v_mma()
{
    extern __shared__ float sm[];
    int t = threadIdx.x, wid = t >> 5, lane = t & 31;
    int z = blockIdx.x, rt = blockIdx.y;
    int mwarp = wid >> 2, nwarp = wid & 3;
    int mbase = mwarp * 64, nbase = nwarp * 32;
    int gr = lane >> 2, gc = lane & 3;
    const int NC = 16;

    int fr = t >> 1, fs = t & 1;
    const float* Ag = g_Utf + (size_t)(rt * 128 + fr) * OMD + z * 512 + fs * 16;
    const float* Bg = g_BinjT + (size_t)fr * OMD + z * 512 + fs * 16;

    int ubase = (4 * fs) ^ (fr & 7);
    uint32_t dA0 = smem_u32(sm + fr * 32 + ubase * 4);
    uint32_t dB0 = dA0 + 16384;

    auto issue = [&](int jc) {
        uint32_t off = (uint32_t)(jc % 3) * 32768u;
        uint32_t da = dA0 + off, db = dB0 + off;
        const float* sa = Ag + jc * 32;
        const float* sb = Bg + jc * 32;
        #pragma unroll
        for (int i = 0; i < 4; i++) {
            cp16(da ^ (i << 4), sa + i * 4);
            cp16(db ^ (i << 4), sb + i * 4);
        }
        asm volatile("cp.async.commit_group;" ::: "memory");
    };

    float acc[4][4][4] = {};
    int su = (2 * gc) ^ gr;

    issue(0); issue(1);
    for (int ic = 0; ic < NC; ic++) {
        if (ic + 2 < NC) { issue(ic + 2);
            asm volatile("cp.async.wait_group 2;" ::: "memory"); }
        else if (ic + 1 < NC)
            asm volatile("cp.async.wait_group 1;" ::: "memory");
        else
            asm volatile("cp.async.wait_group 0;" ::: "memory");
        __syncthreads();

        const float4* As4 = (const float4*)(sm + (ic % 3) * STG_F);
        const float4* Bs4 = As4 + 1024;
        #pragma unroll
        for (int h = 0; h < 2; h++) {
            int suh = su ^ h;
            float4 av[4][2], bv[4];
            #pragma unroll
            for (int mt = 0; mt < 4; mt++) {
                av[mt][0] = As4[(mbase + mt * 16 + gr) * 8 + suh];
                av[mt][1] = As4[(mbase + mt * 16 + 8 + gr) * 8 + suh];
            }
            #pragma unroll
            for (int nt = 0; nt < 4; nt++)
                bv[nt] = Bs4[(nbase + nt * 8 + gr) * 8 + suh];
            #pragma unroll
            for (int s2 = 0; s2 < 2; s2++) {
                #pragma unroll
                for (int mt = 0; mt < 4; mt++) {
                    const float* a0p = (const float*)&av[mt][0];
                    const float* a1p = (const float*)&av[mt][1];
                    #pragma unroll
                    for (int nt = 0; nt < 4; nt++) {
                        const float* bp = (const float*)&bv[nt];
                        mma8(acc[mt][nt], a0p[2*s2], a1p[2*s2],
                             a0p[2*s2+1], a1p[2*s2+1], bp[2*s2], bp[2*s2+1]);
                    }
                }
            }
        }
        __syncthreads();
    }

    float* Vp = g_Vpart + (size_t)z * NCH * NXD;
    #pragma unroll
    for (int mt = 0; mt < 4; mt++) {
        int rg0 = rt * 128 + mbase + mt * 16 + gr;
        int rg1 = rg0 + 8;
        #pragma unroll
        for (int nt = 0; nt < 4; nt++) {
            int col = nbase + nt * 8 + 2 * gc;
            float2 w0 = {acc[mt][nt][0], acc[mt][nt][1]};
            float2 w1 = {acc[mt][nt][2], acc[mt][nt][3]};
            *(float2*)(Vp + (size_t)rg0 * NXD + col) = w0;
            *(float2*)(Vp + (size_t)rg1 * NXD + col) = w1;
        }
    }
}

// ---------------- host launcher ---------------------------------------------
extern "C" void kernel_launch(void* const* d_in, const int* in_sizes, int n_in,
                              void* d_out, int out_size)
{
    const float* u   = (const float*)d_in[0];
    const float* M   = (const float*)d_in[1];
    const float* Bm  = (const float*)d_in[2];
    const float* C   = (const float*)d_in[3];
    const float* x0  = (const float*)d_in[4];
    float* out = (float*)d_out;

    float *pP, *pPtf, *pH, *pUtf;
    cudaGetSymbolAddress((void**)&pP, g_Pstack);
    cudaGetSymbolAddress((void**)&pPtf, g_Ptf);
    cudaGetSymbolAddress((void**)&pH, g_Hstack);
    cudaGetSymbolAddress((void**)&pUtf, g_Utf);

    cudaFuncSetAttribute(gemm_main_mma,
                         cudaFuncAttributeMaxDynamicSharedMemorySize, 98304);
    cudaFuncSetAttribute(gemm_v_mma,
                         cudaFuncAttributeMaxDynamicSharedMemorySize, 98304);
    cudaFuncSetAttribute(chunk_scan,
                         cudaFuncAttributeMaxDynamicSharedMemorySize, 66048);

    copy_bmat<<<32, 256>>>(Bm);                 // GB block 0
    copy_kernel<<<32, 256>>>(pP, C, 64 * 128);  // P block 0 = C
    ef_kernel<<<dim3(4, 4), dim3(32, 32)>>>(M);
    solve_kernel<<<2, 512>>>();

    // 5 doubling steps: widths 64,128,256,512,1024 -> final 2048; A^32 = chain[5]
    for (int s = 0; s < 5; s++) {
        int w = 64 << s;
        fused_double<<<64 + w, dim3(16, 16)>>>(s);
    }

    // H = P @ B_mat (raw fp32 P, 2048 rows)
    mm_nn<<<dim3(4, 128), dim3(16, 16)>>>(pH, pP, Bm, OMD, 64, 128, 128, 64, 64);

    permute_tf32<<<(OMD * NXD) / 256, 256>>>(pPtf, pP, OMD * NXD);
    build_om<<<OMD, 256>>>();
    build_binjT<<<128, 256>>>();
    permute_tf32<<<(NB * TLEN * 64) / 256, 256>>>(pUtf, u, NB * TLEN * 64);

    gemm_v_mma<<<dim3(4, 32), 256, 98304>>>();
    reduce_v<<<2048, 256>>>();
    chunk_scan<<<32, 128, 66048>>>(x0);

    gemm_main_mma<<<dim3(16, 32), 256, 98304>>>(out);
}

// round 15
// speedup vs baseline: 1.7000x; 1.0845x over previous
#include <cuda_runtime.h>
#include <cstdint>
#include <cstddef>

#define NXD  128
#define TLEN 4096
#define NB   32
#define LCH  32
#define KCH  128
#define NCH  (NB*KCH)     // 4096 (batch, chunk) rows
#define OMD  2048         // LCH*64 : Omega dim, Y cols per (b,chunk) row
#define STG_F 8192        // floats per pipeline stage (A 4096 + B 4096)

// ---------------- static device workspaces ----------------------------------
__device__ float g_E[NXD*NXD];
__device__ float g_F[NXD*NXD];
__device__ float g_chain[7*NXD*NXD];          // A^(2^s), s=0..5 used
__device__ float g_Pstack[OMD*NXD];           // P_i = C A^i (raw fp32), 2048x128
__device__ float g_Ptf[OMD*NXD];              // P permuted + tf32
__device__ float g_GBwide[NXD*OMD];           // [A^m B] blocks (128 x 2048)
__device__ float g_BinjT[NXD*OMD];            // injection op^T, permuted+tf32
__device__ float g_Hstack[OMD*64];            // H_m = C A^m B (2048 x 64)
__device__ float g_Om[(size_t)OMD*OMD];       // Omega, permuted+tf32 (16MB)
__device__ float g_Utf[(size_t)NB*TLEN*64];   // U permuted + tf32 (32MB)
__device__ float g_V[NCH*NXD];
__device__ float g_Xp[NCH*NXD];               // chunk states, permuted+tf32
__device__ float g_Vpart[4*NCH*NXD];
__device__ unsigned long long g_fac[128*128]; // {fac:hi32, seq:lo32} per (k,row)

// ---------------- helpers ----------------------------------------------------
__device__ __forceinline__ float to_tf32(float x) {
    uint32_t u;
    asm("cvt.rna.tf32.f32 %0, %1;" : "=r"(u) : "f"(x));
    return __uint_as_float(u);
}
__device__ __forceinline__ uint32_t smem_u32(const void* p) {
    uint32_t a;
    asm("{ .reg .u64 t; cvta.to.shared.u64 t, %1; cvt.u32.u64 %0, t; }"
        : "=r"(a) : "l"(p));
    return a;
}
__device__ __forceinline__ void mma8(float* c, float a0, float a1, float a2,
                                     float a3, float b0, float b1) {
    asm volatile(
        "mma.sync.aligned.m16n8k8.row.col.f32.tf32.tf32.f32 "
        "{%0,%1,%2,%3}, {%4,%5,%6,%7}, {%8,%9}, {%0,%1,%2,%3};"
        : "+f"(c[0]), "+f"(c[1]), "+f"(c[2]), "+f"(c[3])
        : "r"(__float_as_uint(a0)), "r"(__float_as_uint(a1)),
          "r"(__float_as_uint(a2)), "r"(__float_as_uint(a3)),
          "r"(__float_as_uint(b0)), "r"(__float_as_uint(b1)));
}
__device__ __forceinline__ void cp16(uint32_t dst, const float* src) {
    asm volatile("cp.async.cg.shared.global [%0], [%1], 16;"
                 :: "r"(dst), "l"(src));
}
// permutation: source k (within 32-block) stored at pos (k%4)*8 + k/4
__device__ __forceinline__ int kperm(int j) { return ((j & 3) << 3) | (j >> 2); }

// ---------------- E, F from M ------------------------------------------------
__global__ void ef_kernel(const float* __restrict__ M)
{
    __shared__ float s0i[32][33], s1i[32][33], s0j[32][33], s1j[32][33];
    int tx = threadIdx.x, ty = threadIdx.y;
    int i0 = blockIdx.y * 32, j0 = blockIdx.x * 32;
    float e0 = 0.f, e1 = 0.f, f = 0.f;
    for (int kt = 0; kt < 256; kt += 32) {
        s0i[ty][tx] = M[(i0 + ty) * 256 + kt + tx];
        s1i[ty][tx] = M[(128 + i0 + ty) * 256 + kt + tx];
        s0j[ty][tx] = M[(j0 + ty) * 256 + kt + tx];
        s1j[ty][tx] = M[(128 + j0 + ty) * 256 + kt + tx];
        __syncthreads();
        #pragma unroll
        for (int kk = 0; kk < 32; kk++) {
            float a0 = s0i[ty][kk], a1 = s1i[ty][kk];
            float b0 = s0j[tx][kk], b1 = s1j[tx][kk];
            e0 += a0 * b0; e1 += a1 * b1; f += a1 * b0;
        }
        __syncthreads();
    }
    int i = i0 + ty, j = j0 + tx;
    float e = 0.5f * (e0 + e1);
    if (i == j) e += 1e-9f;
    g_E[i * NXD + j] = e;
    g_F[i * NXD + j] = f;
}

// ---------------- 2-CTA Gauss-Jordan: solve E A = F (R13 proven) -------------
__global__ void __launch_bounds__(512) solve_kernel()
{
    __shared__ float4 prow4[2][32];
    __shared__ float  sfac[2][128];
    int t = threadIdx.x;
    int cq = t >> 7, rq = t & 127;

    bool isE = (blockIdx.x == 0);
    float4 w[8];
    {
        const float* src = (isE ? g_E : g_F) + rq * 128 + cq * 32;
        #pragma unroll
        for (int i = 0; i < 8; i++) w[i] = ((const float4*)src)[i];
    }

    if (isE) {
        for (int k = 0; k < 128; k++) {
            int b = k & 1;
            if (cq == (k >> 5)) {
                int jf4 = (k >> 2) & 7, jc = k & 3;
                float4 v = w[0];
                #pragma unroll
                for (int i = 1; i < 8; i++) if (jf4 == i) v = w[i];
                float f = (jc == 0) ? v.x : (jc == 1) ? v.y
                        : (jc == 2) ? v.z : v.w;
                sfac[b][rq] = f;
            }
            if (rq == k) {
                #pragma unroll
                for (int i = 0; i < 8; i++) prow4[b][cq * 8 + i] = w[i];
            }
            __syncthreads();

            float pv = sfac[b][k];
            float r;
            asm("rcp.approx.f32 %0, %1;" : "=f"(r) : "f"(pv));
            r = r * (2.0f - pv * r);
            r = r * (2.0f - pv * r);

            float facv;
            if (rq == k) {
                facv = r;
                #pragma unroll
                for (int i = 0; i < 8; i++) {
                    w[i].x *= r; w[i].y *= r; w[i].z *= r; w[i].w *= r;
                }
            } else {
                float factor = sfac[b][rq] * r;
                facv = factor;
                #pragma unroll
                for (int i = 0; i < 8; i++) {
                    float4 p = prow4[b][cq * 8 + i];
                    w[i].x -= factor * p.x; w[i].y -= factor * p.y;
                    w[i].z -= factor * p.z; w[i].w -= factor * p.w;
                }
            }
            if (cq == 0) {
                unsigned long long pk =
                    ((unsigned long long)__float_as_uint(facv) << 32)
                    | (unsigned)(k + 1);
                asm volatile("st.release.gpu.b64 [%0], %1;"
                             :: "l"(g_fac + k * 128 + rq), "l"(pk) : "memory");
            }
        }
    } else {
        for (int k = 0; k < 128; k++) {
            int b = k & 1;
            if (rq == k) {
                #pragma unroll
                for (int i = 0; i < 8; i++) prow4[b][cq * 8 + i] = w[i];
            }
            __syncthreads();

            unsigned long long v;
            const unsigned long long* ptr = g_fac + k * 128 + rq;
            do {
                asm volatile("ld.acquire.gpu.b64 %0, [%1];"
                             : "=l"(v) : "l"(ptr) : "memory");
            } while ((unsigned)v != (unsigned)(k + 1));
            float fac = __uint_as_float((unsigned)(v >> 32));

            if (rq == k) {
                #pragma unroll
                for (int i = 0; i < 8; i++) {
                    w[i].x *= fac; w[i].y *= fac; w[i].z *= fac; w[i].w *= fac;
                }
            } else {
                #pragma unroll
                for (int i = 0; i < 8; i++) {
                    float4 p = prow4[b][cq * 8 + i];
                    w[i].x -= fac * p.x; w[i].y -= fac * p.y;
                    w[i].z -= fac * p.z; w[i].w -= fac * p.w;
                }
            }
        }
        float* dst = g_chain + rq * 128 + cq * 32;
        #pragma unroll
        for (int i = 0; i < 8; i++) ((float4*)dst)[i] = w[i];
    }
}

// ---------------- generic tiled GEMM C = A*B (row-major) for H ---------------
__global__ void mm_nn(float* __restrict__ Cc, const float* __restrict__ A,
                      const float* __restrict__ B,
                      int Mm, int Nn, int Kk, int lda, int ldb, int ldc)
{
    __shared__ float As[16][17], Bs[16][17];
    int tx = threadIdx.x, ty = threadIdx.y;
    int row = blockIdx.y * 16 + ty, col = blockIdx.x * 16 + tx;
    float acc = 0.f;
    for (int k0 = 0; k0 < Kk; k0 += 16) {
        As[ty][tx] = (row < Mm) ? A[row * lda + k0 + tx] : 0.f;
        Bs[ty][tx] = (col < Nn) ? B[(k0 + ty) * ldb + col] : 0.f;
        __syncthreads();
        #pragma unroll
        for (int kk = 0; kk < 16; kk++) acc += As[ty][kk] * Bs[kk][tx];
        __syncthreads();
    }
    if (row < Mm && col < Nn) Cc[row * ldc + col] = acc;
}

// ---------------- fused doubling step: chain^2, GB extend, P extend ----------
__global__ void fused_double(int s)
{
    int w = 64 << s;
    int t1 = w >> 1;
    int bid = blockIdx.x;
    const float* chain_s = g_chain + s * 16384;
    const float *Ain, *Bin; float* Cout;
    int bx, by, lda, ldb, ldc;
    if (bid < 64) {
        bx = bid & 7; by = bid >> 3;
        Ain = chain_s; Bin = chain_s; Cout = g_chain + (s + 1) * 16384;
        lda = 128; ldb = 128; ldc = 128;
    } else if (bid < 64 + t1) {
        int r = bid - 64; int nt = w >> 4;
        bx = r % nt; by = r / nt;
        Ain = chain_s; Bin = g_GBwide; Cout = g_GBwide + w;
        lda = 128; ldb = OMD; ldc = OMD;
    } else {
        int r = bid - 64 - t1;
        bx = r & 7; by = r >> 3;
        Ain = g_Pstack; Bin = chain_s; Cout = g_Pstack + w * 128;
        lda = 128; ldb = 128; ldc = 128;
    }
    __shared__ float As[16][17], Bs[16][17];
    int tx = threadIdx.x, ty = threadIdx.y;
    int row = by * 16 + ty, col = bx * 16 + tx;
    float acc = 0.f;
    for (int k0 = 0; k0 < 128; k0 += 16) {
        As[ty][tx] = Ain[row * lda + k0 + tx];
        Bs[ty][tx] = Bin[(k0 + ty) * ldb + col];
        __syncthreads();
        #pragma unroll
        for (int kk = 0; kk < 16; kk++) acc += As[ty][kk] * Bs[kk][tx];
        __syncthreads();
    }
    Cout[row * ldc + col] = acc;
}

// ---------------- small helpers ---------------------------------------------
__global__ void copy_kernel(float* __restrict__ dst, const float* __restrict__ src, int n)
{
    int i = blockIdx.x * blockDim.x + threadIdx.x;
    if (i < n) dst[i] = src[i];
}

__global__ void copy_bmat(const float* __restrict__ Bm)
{
    int i = blockIdx.x * blockDim.x + threadIdx.x;
    if (i < 128 * 64) {
        int r = i >> 6, c = i & 63;
        g_GBwide[r * OMD + c] = Bm[i];
    }
}

// permute within 32-float blocks + tf32 round
__global__ void permute_tf32(float* __restrict__ dst, const float* __restrict__ src,
                             int n)
{
    int i = blockIdx.x * blockDim.x + threadIdx.x;
    if (i >= n) return;
    int q = i & 31;
    int j = ((q & 7) << 2) | (q >> 3);       // inverse permutation
    dst[i] = to_tf32(src[(i - q) + j]);
}

// BinjT[n][perm(q)] = tf32( (A^(31-j) B)[n][uu] ),  q = j*64+uu
__global__ void build_binjT()
{
    int n = blockIdx.x;
    for (int q = threadIdx.x; q < OMD; q += blockDim.x) {
        float v = g_GBwide[n * OMD + (31 - (q >> 6)) * 64 + (q & 63)];
        g_BinjT[n * OMD + (q & ~31) + kperm(q & 31)] = to_tf32(v);
    }
}

// Om[p][perm(q)] = (j<i) ? tf32(H_{i-1-j}[o][uu]) : 0   p=(i,o), i,j 0..31
__global__ void build_om()
{
    int p = blockIdx.x;
    int i = p >> 6, o = p & 63;
    size_t base = (size_t)p * OMD;
    for (int q = threadIdx.x; q < OMD; q += blockDim.x) {
        int j = q >> 6, uu = q & 63;
        float v = 0.f;
        if (j < i) v = to_tf32(g_Hstack[(((i - 1 - j) << 6) + o) * 64 + uu]);
        g_Om[base + (q & ~31) + kperm(q & 31)] = v;
    }
}

__global__ void reduce_v()
{
    int i = blockIdx.x * blockDim.x + threadIdx.x;
    if (i < NCH * NXD) {
        float s = 0.f;
        #pragma unroll
        for (int z = 0; z < 4; z++) s += g_Vpart[(size_t)z * NCH * NXD + i];
        g_V[i] = s;
    }
}

// ---------------- chunk-level scan (A^32, 127 steps) -------------------------
__global__ void __launch_bounds__(128) chunk_scan(const float* __restrict__ x0)
{
    extern __shared__ float At[];        // 128*129 floats
    __shared__ float xs[128];
    int b = blockIdx.x, n = threadIdx.x;
    int np = (n & ~31) | kperm(n & 31);
    const float* A32 = g_chain + 5 * NXD * NXD;
    for (int idx = n; idx < 128 * 128; idx += 128) {
        int row = idx >> 7, col = idx & 127;
        At[col * 129 + row] = A32[idx];
    }
    xs[n] = x0[n];
    __syncthreads();
    g_Xp[(b * KCH + 0) * NXD + np] = to_tf32(xs[n]);
    for (int k = 0; k < KCH - 1; k++) {
        float acc = g_V[(b * KCH + k) * NXD + n];
        #pragma unroll 8
        for (int m = 0; m < 128; m++) acc += At[m * 129 + n] * xs[m];
        __syncthreads();
        xs[n] = acc;
        __syncthreads();
        g_Xp[(b * KCH + k + 1) * NXD + np] = to_tf32(acc);
    }
}

// ---------------- main GEMM (U part only): out = Uc * Om^T -------------------
// CTA 128x128, 8 warps (2x4), warp tile 64x32, BK=32, 3-stage, 2 CTAs/SM.
// No Xp dependency: the X*P^T tail is applied by gemm_tail_mma afterwards.
__global__ void __launch_bounds__(256, 2) gemm_mainU_mma(float* __restrict__ out)
{
    extern __shared__ float sm[];
    int t = threadIdx.x, wid = t >> 5, lane = t & 31;
    int ct = 15 - blockIdx.x, rt = blockIdx.y;
    int mwarp = wid >> 2, nwarp = wid & 3;
    int mbase = mwarp * 64, nbase = nwarp * 32;
    int gr = lane >> 2, gc = lane & 3;

    int NC = (2 * ct + 1) * 2;         // K chunks (32 each)

    int fr = t >> 1, fs = t & 1;
    const float* AgU = g_Utf + (size_t)(rt * 128 + fr) * OMD + fs * 16;
    const float* BgO = g_Om  + (size_t)(ct * 128 + fr) * OMD + fs * 16;

    int ubase = (4 * fs) ^ (fr & 7);
    uint32_t dA0 = smem_u32(sm + fr * 32 + ubase * 4);
    uint32_t dB0 = dA0 + 16384;

    auto issue = [&](int jc) {
        uint32_t off = (uint32_t)(jc % 3) * 32768u;
        uint32_t da = dA0 + off, db = dB0 + off;
        const float* sa = AgU + jc * 32;
        const float* sb = BgO + jc * 32;
        #pragma unroll
        for (int i = 0; i < 4; i++) {
            cp16(da ^ (i << 4), sa + i * 4);
            cp16(db ^ (i << 4), sb + i * 4);
        }
        asm volatile("cp.async.commit_group;" ::: "memory");
    };

    float acc[4][4][4] = {};
    int su = (2 * gc) ^ gr;

    issue(0);
    if (NC > 1) issue(1);

    for (int ic = 0; ic < NC; ic++) {
        if (ic + 2 < NC) { issue(ic + 2);
            asm volatile("cp.async.wait_group 2;" ::: "memory"); }
        else if (ic + 1 < NC)
            asm volatile("cp.async.wait_group 1;" ::: "memory");
        else
            asm volatile("cp.async.wait_group 0;" ::: "memory");
        __syncthreads();

        const float4* As4 = (const float4*)(sm + (ic % 3) * STG_F);
        const float4* Bs4 = As4 + 1024;
        #pragma unroll
        for (int h = 0; h < 2; h++) {
            int suh = su ^ h;
            float4 av[4][2], bv[4];
            #pragma unroll
            for (int mt = 0; mt < 4; mt++) {
                av[mt][0] = As4[(mbase + mt * 16 + gr) * 8 + suh];
                av[mt][1] = As4[(mbase + mt * 16 + 8 + gr) * 8 + suh];
            }
            #pragma unroll
            for (int nt = 0; nt < 4; nt++)
                bv[nt] = Bs4[(nbase + nt * 8 + gr) * 8 + suh];
            #pragma unroll
            for (int s2 = 0; s2 < 2; s2++) {
                #pragma unroll
                for (int mt = 0; mt < 4; mt++) {
                    const float* a0p = (const float*)&av[mt][0];
                    const float* a1p = (const float*)&av[mt][1];
                    #pragma unroll
                    for (int nt = 0; nt < 4; nt++) {
                        const float* bp = (const float*)&bv[nt];
                        mma8(acc[mt][nt], a0p[2*s2], a1p[2*s2],
                             a0p[2*s2+1], a1p[2*s2+1], bp[2*s2], bp[2*s2+1]);
                    }
                }
            }
        }
        __syncthreads();
    }

    #pragma unroll
    for (int mt = 0; mt < 4; mt++) {
        int rg0 = rt * 128 + mbase + mt * 16 + gr;
        int rg1 = rg0 + 8;
        float* base0 = out + (size_t)rg0 * OMD;
        float* base1 = out + (size_t)rg1 * OMD;
        #pragma unroll
        for (int nt = 0; nt < 4; nt++) {
            int p = ct * 128 + nbase + nt * 8 + 2 * gc;
            float2 w0 = {acc[mt][nt][0], acc[mt][nt][1]};
            float2 w1 = {acc[mt][nt][2], acc[mt][nt][3]};
            *(float2*)(base0 + p) = w0;
            *(float2*)(base1 + p) = w1;
        }
    }
}

// ---------------- tail GEMM: out += Xp * Ptf^T (K = 128) ---------------------
__global__ void __launch_bounds__(256, 2) gemm_tail_mma(float* __restrict__ out)
{
    extern __shared__ float sm[];
    int t = threadIdx.x, wid = t >> 5, lane = t & 31;
    int ct = blockIdx.x, rt = blockIdx.y;
    int mwarp = wid >> 2, nwarp = wid & 3;
    int mbase = mwarp * 64, nbase = nwarp * 32;
    int gr = lane >> 2, gc = lane & 3;
    const int NC = 4;

    int fr = t >> 1, fs = t & 1;
    const float* Ag = g_Xp  + (rt * 128 + fr) * NXD + fs * 16;
    const float* Bg = g_Ptf + (ct * 128 + fr) * NXD + fs * 16;

    int ubase = (4 * fs) ^ (fr & 7);
    uint32_t dA0 = smem_u32(sm + fr * 32 + ubase * 4);
    uint32_t dB0 = dA0 + 16384;

    auto issue = [&](int jc) {
        uint32_t off = (uint32_t)(jc % 3) * 32768u;
        uint32_t da = dA0 + off, db = dB0 + off;
        const float* sa = Ag + jc * 32;
        const float* sb = Bg + jc * 32;
        #pragma unroll
        for (int i = 0; i < 4; i++) {
            cp16(da ^ (i << 4), sa + i * 4);
            cp16(db ^ (i << 4), sb + i * 4);
        }
        asm volatile("cp.async.commit_group;" ::: "memory");
    };

    float acc[4][4][4] = {};
    int su = (2 * gc) ^ gr;

    issue(0); issue(1);
    for (int ic = 0; ic < NC; ic++) {
        if (ic + 2 < NC) { issue(ic + 2);
            asm volatile("cp.async.wait_group 2;" ::: "memory"); }
        else if (ic + 1 < NC)
            asm volatile("cp.async.wait_group 1;" ::: "memory");
        else
            asm volatile("cp.async.wait_group 0;" ::: "memory");
        __syncthreads();

        const float4* As4 = (const float4*)(sm + (ic % 3) * STG_F);
        const float4* Bs4 = As4 + 1024;
        #pragma unroll
        for (int h = 0; h < 2; h++) {
            int suh = su ^ h;
            float4 av[4][2], bv[4];
            #pragma unroll
            for (int mt = 0; mt < 4; mt++) {
                av[mt][0] = As4[(mbase + mt * 16 + gr) * 8 + suh];
                av[mt][1] = As4[(mbase + mt * 16 + 8 + gr) * 8 + suh];
            }
            #pragma unroll
            for (int nt = 0; nt < 4; nt++)
                bv[nt] = Bs4[(nbase + nt * 8 + gr) * 8 + suh];
            #pragma unroll
            for (int s2 = 0; s2 < 2; s2++) {
                #pragma unroll
                for (int mt = 0; mt < 4; mt++) {
                    const float* a0p = (const float*)&av[mt][0];
                    const float* a1p = (const float*)&av[mt][1];
                    #pragma unroll
                    for (int nt = 0; nt < 4; nt++) {
                        const float* bp = (const float*)&bv[nt];
                        mma8(acc[mt][nt], a0p[2*s2], a1p[2*s2],
                             a0p[2*s2+1], a1p[2*s2+1], bp[2*s2], bp[2*s2+1]);
                    }
                }
            }
        }
        __syncthreads();
    }

    // accumulate into out
    #pragma unroll
    for (int mt = 0; mt < 4; mt++) {
        int rg0 = rt * 128 + mbase + mt * 16 + gr;
        int rg1 = rg0 + 8;
        float* base0 = out + (size_t)rg0 * OMD;
        float* base1 = out + (size_t)rg1 * OMD;
        #pragma unroll
        for (int nt = 0; nt < 4; nt++) {
            int p = ct * 128 + nbase + nt * 8 + 2 * gc;
            float2 o0 = *(float2*)(base0 + p);
            float2 o1 = *(float2*)(base1 + p);
            o0.x += acc[mt][nt][0]; o0.y += acc[mt][nt][1];
            o1.x += acc[mt][nt][2]; o1.y += acc[mt][nt][3];
            *(float2*)(base0 + p) = o0;
            *(float2*)(base1 + p) = o1;
        }
    }
}

// ---------------- injection GEMM: 256 threads / 8 warps, 2 CTAs/SM -----------
__global__ void __launch_bounds__(256, 2) gemm_v_mma()
{
    extern __shared__ float sm[];
    int t = threadIdx.x, wid = t >> 5, lane = t & 31;
    int z = blockIdx.x, rt = blockIdx.y;
    int mwarp = wid >> 2, nwarp = wid & 3;
    int mbase = mwarp * 64, nbase = nwarp * 32;
    int gr = lane >> 2, gc = lane & 3;
    const int NC = 16;

    int fr = t >> 1, fs = t & 1;
    const float* Ag = g_Utf + (size_t)(rt * 128 + fr) * OMD + z * 512 + fs * 16;
    const float* Bg = g_BinjT + (size_t)fr * OMD + z * 512 + fs * 16;

    int ubase = (4 * fs) ^ (fr & 7);
    uint32_t dA0 = smem_u32(sm + fr * 32 + ubase * 4);
    uint32_t dB0 = dA0 + 16384;

    auto issue = [&](int jc) {
        uint32_t off = (uint32_t)(jc % 3) * 32768u;
        uint32_t da = dA0 + off, db = dB0 + off;
        const float* sa = Ag + jc * 32;
        const float* sb = Bg + jc * 32;
        #pragma unroll
        for (int i = 0; i < 4; i++) {
            cp16(da ^ (i << 4), sa + i * 4);
            cp16(db ^ (i << 4), sb + i * 4);
        }
        asm volatile("cp.async.commit_group;" ::: "memory");
    };

    float acc[4][4][4] = {};
    int su = (2 * gc) ^ gr;

    issue(0); issue(1);
    for (int ic = 0; ic < NC; ic++) {
        if (ic + 2 < NC) { issue(ic + 2);
            asm volatile("cp.async.wait_group 2;" ::: "memory"); }
        else if (ic + 1 < NC)
            asm volatile("cp.async.wait_group 1;" ::: "memory");
        else
            asm volatile("cp.async.wait_group 0;" ::: "memory");
        __syncthreads();

        const float4* As4 = (const float4*)(sm + (ic % 3) * STG_F);
        const float4* Bs4 = As4 + 1024;
        #pragma unroll
        for (int h = 0; h < 2; h++) {
            int suh = su ^ h;
            float4 av[4][2], bv[4];
            #pragma unroll
            for (int mt = 0; mt < 4; mt++) {
                av[mt][0] = As4[(mbase + mt * 16 + gr) * 8 + suh];
                av[mt][1] = As4[(mbase + mt * 16 + 8 + gr) * 8 + suh];
            }
            #pragma unroll
            for (int nt = 0; nt < 4; nt++)
                bv[nt] = Bs4[(nbase + nt * 8 + gr) * 8 + suh];
            #pragma unroll
            for (int s2 = 0; s2 < 2; s2++) {
                #pragma unroll
                for (int mt = 0; mt < 4; mt++) {
                    const float* a0p = (const float*)&av[mt][0];
                    const float* a1p = (const float*)&av[mt][1];
                    #pragma unroll
                    for (int nt = 0; nt < 4; nt++) {
                        const float* bp = (const float*)&bv[nt];
                        mma8(acc[mt][nt], a0p[2*s2], a1p[2*s2],
                             a0p[2*s2+1], a1p[2*s2+1], bp[2*s2], bp[2*s2+1]);
                    }
                }
            }
        }
        __syncthreads();
    }

    float* Vp = g_Vpart + (size_t)z * NCH * NXD;
    #pragma unroll
    for (int mt = 0; mt < 4; mt++) {
        int rg0 = rt * 128 + mbase + mt * 16 + gr;
        int rg1 = rg0 + 8;
        #pragma unroll
        for (int nt = 0; nt < 4; nt++) {
            int col = nbase + nt * 8 + 2 * gc;
            float2 w0 = {acc[mt][nt][0], acc[mt][nt][1]};
            float2 w1 = {acc[mt][nt][2], acc[mt][nt][3]};
            *(float2*)(Vp + (size_t)rg0 * NXD + col) = w0;
            *(float2*)(Vp + (size_t)rg1 * NXD + col) = w1;
        }
    }
}

// ---------------- host launcher ---------------------------------------------
extern "C" void kernel_launch(void* const* d_in, const int* in_sizes, int n_in,
                              void* d_out, int out_size)
{
    const float* u   = (const float*)d_in[0];
    const float* M   = (const float*)d_in[1];
    const float* Bm  = (const float*)d_in[2];
    const float* C   = (const float*)d_in[3];
    const float* x0  = (const float*)d_in[4];
    float* out = (float*)d_out;

    float *pP, *pPtf, *pH, *pUtf;
    cudaGetSymbolAddress((void**)&pP, g_Pstack);
    cudaGetSymbolAddress((void**)&pPtf, g_Ptf);
    cudaGetSymbolAddress((void**)&pH, g_Hstack);
    cudaGetSymbolAddress((void**)&pUtf, g_Utf);

    static cudaStream_t s2 = nullptr;
    static cudaEvent_t e0 = nullptr, e2 = nullptr, e3 = nullptr, e4 = nullptr;
    if (s2 == nullptr) {
        cudaStreamCreateWithFlags(&s2, cudaStreamNonBlocking);
        cudaEventCreateWithFlags(&e0, cudaEventDisableTiming);
        cudaEventCreateWithFlags(&e2, cudaEventDisableTiming);
        cudaEventCreateWithFlags(&e3, cudaEventDisableTiming);
        cudaEventCreateWithFlags(&e4, cudaEventDisableTiming);
        cudaFuncSetAttribute(gemm_mainU_mma,
                             cudaFuncAttributeMaxDynamicSharedMemorySize, 98304);
        cudaFuncSetAttribute(gemm_tail_mma,
                             cudaFuncAttributeMaxDynamicSharedMemorySize, 98304);
        cudaFuncSetAttribute(gemm_v_mma,
                             cudaFuncAttributeMaxDynamicSharedMemorySize, 98304);
        cudaFuncSetAttribute(chunk_scan,
                             cudaFuncAttributeMaxDynamicSharedMemorySize, 66048);
    }

    // ---- fork: U permute runs on s2 concurrently with the solve chain ----
    cudaEventRecord(e0, 0);
    cudaStreamWaitEvent(s2, e0, 0);
    permute_tf32<<<(NB * TLEN * 64) / 256, 256, 0, s2>>>(pUtf, u, NB * TLEN * 64);
    cudaEventRecord(e4, s2);

    // ---- default stream: A-matrix chain ----
    copy_bmat<<<32, 256>>>(Bm);                 // GB block 0
    copy_kernel<<<32, 256>>>(pP, C, 64 * 128);  // P block 0 = C
    ef_kernel<<<dim3(4, 4), dim3(32, 32)>>>(M);
    solve_kernel<<<2, 512>>>();

    for (int s = 0; s < 5; s++) {
        int w = 64 << s;
        fused_double<<<64 + w, dim3(16, 16)>>>(s);
    }

    mm_nn<<<dim3(4, 128), dim3(16, 16)>>>(pH, pP, Bm, OMD, 64, 128, 128, 64, 64);
    permute_tf32<<<(OMD * NXD) / 256, 256>>>(pPtf, pP, OMD * NXD);
    build_om<<<OMD, 256>>>();
    build_binjT<<<128, 256>>>();

    // ---- fork: injection chain on s2 concurrently with the main GEMM ----
    cudaEventRecord(e2, 0);
    cudaStreamWaitEvent(s2, e2, 0);
    gemm_v_mma<<<dim3(4, 32), 256, 98304, s2>>>();
    reduce_v<<<2048, 256, 0, s2>>>();
    chunk_scan<<<32, 128, 66048, s2>>>(x0);
    cudaEventRecord(e3, s2);

    // ---- default stream: main GEMM (U part), then join, then tail ----
    cudaStreamWaitEvent(0, e4, 0);
    gemm_mainU_mma<<<dim3(16, 32), 256, 98304>>>(out);
    cudaStreamWaitEvent(0, e3, 0);
    gemm_tail_mma<<<dim3(16, 32), 256, 98304>>>(out);
}

// round 16
// speedup vs baseline: 1.7608x; 1.0357x over previous
#include <cuda_runtime.h>
#include <cstdint>
#include <cstddef>

#define NXD  128
#define TLEN 4096
#define NB   32
#define LCH  32
#define KCH  128
#define NCH  (NB*KCH)     // 4096 (batch, chunk) rows
#define OMD  2048         // LCH*64 : Omega dim, Y cols per (b,chunk) row
#define STG_F 8192        // floats per pipeline stage (A 4096 + B 4096)

// ---------------- static device workspaces ----------------------------------
__device__ float g_E[NXD*NXD];
__device__ float g_F[NXD*NXD];
__device__ float g_chain[7*NXD*NXD];          // A^(2^s), s=0..5 used
__device__ float g_Pstack[OMD*NXD];           // P_i = C A^i (raw fp32), 2048x128
__device__ float g_Ptf[OMD*NXD];              // P permuted + tf32
__device__ float g_GBwide[NXD*OMD];           // [A^m B] blocks (128 x 2048)
__device__ float g_BinjT[NXD*OMD];            // injection op^T, permuted+tf32
__device__ float g_Hstack[OMD*64];            // H_m = C A^m B (2048 x 64)
__device__ float g_Om[(size_t)OMD*OMD];       // Omega, permuted+tf32 (16MB)
__device__ float g_Utf[(size_t)NB*TLEN*64];   // U permuted + tf32 (32MB)
__device__ float g_V[NCH*NXD];
__device__ float g_Xp[NCH*NXD];               // chunk states, permuted+tf32
__device__ float g_Vpart[4*NCH*NXD];
__device__ float g_prow[128*256];             // scaled pivot rows
__device__ unsigned g_seq[128];               // pivot publication flags

// ---------------- helpers ----------------------------------------------------
__device__ __forceinline__ float to_tf32(float x) {
    uint32_t u;
    asm("cvt.rna.tf32.f32 %0, %1;" : "=r"(u) : "f"(x));
    return __uint_as_float(u);
}
__device__ __forceinline__ uint32_t smem_u32(const void* p) {
    uint32_t a;
    asm("{ .reg .u64 t; cvta.to.shared.u64 t, %1; cvt.u32.u64 %0, t; }"
        : "=r"(a) : "l"(p));
    return a;
}
__device__ __forceinline__ void mma8(float* c, float a0, float a1, float a2,
                                     float a3, float b0, float b1) {
    asm volatile(
        "mma.sync.aligned.m16n8k8.row.col.f32.tf32.tf32.f32 "
        "{%0,%1,%2,%3}, {%4,%5,%6,%7}, {%8,%9}, {%0,%1,%2,%3};"
        : "+f"(c[0]), "+f"(c[1]), "+f"(c[2]), "+f"(c[3])
        : "r"(__float_as_uint(a0)), "r"(__float_as_uint(a1)),
          "r"(__float_as_uint(a2)), "r"(__float_as_uint(a3)),
          "r"(__float_as_uint(b0)), "r"(__float_as_uint(b1)));
}
__device__ __forceinline__ void cp16(uint32_t dst, const float* src) {
    asm volatile("cp.async.cg.shared.global [%0], [%1], 16;"
                 :: "r"(dst), "l"(src));
}
// permutation: source k (within 32-block) stored at pos (k%4)*8 + k/4
__device__ __forceinline__ int kperm(int j) { return ((j & 3) << 3) | (j >> 2); }

// ---------------- E, F from M ------------------------------------------------
__global__ void ef_kernel(const float* __restrict__ M)
{
    __shared__ float s0i[32][33], s1i[32][33], s0j[32][33], s1j[32][33];
    int tx = threadIdx.x, ty = threadIdx.y;
    int i0 = blockIdx.y * 32, j0 = blockIdx.x * 32;
    float e0 = 0.f, e1 = 0.f, f = 0.f;
    for (int kt = 0; kt < 256; kt += 32) {
        s0i[ty][tx] = M[(i0 + ty) * 256 + kt + tx];
        s1i[ty][tx] = M[(128 + i0 + ty) * 256 + kt + tx];
        s0j[ty][tx] = M[(j0 + ty) * 256 + kt + tx];
        s1j[ty][tx] = M[(128 + j0 + ty) * 256 + kt + tx];
        __syncthreads();
        #pragma unroll
        for (int kk = 0; kk < 32; kk++) {
            float a0 = s0i[ty][kk], a1 = s1i[ty][kk];
            float b0 = s0j[tx][kk], b1 = s1j[tx][kk];
            e0 += a0 * b0; e1 += a1 * b1; f += a1 * b0;
        }
        __syncthreads();
    }
    int i = i0 + ty, j = j0 + tx;
    float e = 0.5f * (e0 + e1);
    if (i == j) e += 1e-9f;
    g_E[i * NXD + j] = e;
    g_F[i * NXD + j] = f;
}

// ---------------- 8-CTA warp-per-row pipelined Gauss-Jordan ------------------
// grid 8 x 512 threads. Warp w of CTA c owns augmented row (c*16 + w) fully in
// registers (8 floats/thread, cols lane*8..lane*8+7 of [E|F]). Pivot k's owner
// warp scales its row by rcp(pivot), publishes it + a fenced seq flag; all
// other warps acquire-spin, load the row from L2, and update. No barriers.
__global__ void __launch_bounds__(512) solve_kernel()
{
    int t = threadIdx.x;
    int wr = t >> 5, lane = t & 31;
    int grow = blockIdx.x * 16 + wr;

    float4 w0, w1;
    {
        const float* base = (lane < 16) ? (g_E + grow * 128 + lane * 8)
                                        : (g_F + grow * 128 + (lane - 16) * 8);
        w0 = ((const float4*)base)[0];
        w1 = ((const float4*)base)[1];
    }

    for (int k = 0; k < 128; k++) {
        int srcl = k >> 3, comp = k & 7;
        float myk;
        {
            float4 v = (comp < 4) ? w0 : w1;
            int c2 = comp & 3;
            myk = (c2 == 0) ? v.x : (c2 == 1) ? v.y : (c2 == 2) ? v.z : v.w;
        }
        float fac = __shfl_sync(0xFFFFFFFFu, myk, srcl);

        if (grow == k) {
            float r;
            asm("rcp.approx.f32 %0, %1;" : "=f"(r) : "f"(fac));
            r = r * (2.0f - fac * r);
            r = r * (2.0f - fac * r);
            w0.x *= r; w0.y *= r; w0.z *= r; w0.w *= r;
            w1.x *= r; w1.y *= r; w1.z *= r; w1.w *= r;
            float* pr = g_prow + k * 256 + lane * 8;
            ((float4*)pr)[0] = w0;
            ((float4*)pr)[1] = w1;
            __syncwarp();
            if (lane == 0) {
                asm volatile("fence.acq_rel.gpu;" ::: "memory");
                asm volatile("st.relaxed.gpu.b32 [%0], %1;"
                             :: "l"(g_seq + k), "r"((unsigned)(k + 1)) : "memory");
            }
        } else {
            unsigned v;
            const unsigned* fp = g_seq + k;
            do {
                asm volatile("ld.acquire.gpu.b32 %0, [%1];"
                             : "=r"(v) : "l"(fp) : "memory");
            } while (v != (unsigned)(k + 1));
            const float* pr = g_prow + k * 256 + lane * 8;
            float4 p0 = ((const float4*)pr)[0];
            float4 p1 = ((const float4*)pr)[1];
            w0.x -= fac * p0.x; w0.y -= fac * p0.y;
            w0.z -= fac * p0.z; w0.w -= fac * p0.w;
            w1.x -= fac * p1.x; w1.y -= fac * p1.y;
            w1.z -= fac * p1.z; w1.w -= fac * p1.w;
        }
    }

    if (lane >= 16) {
        float* dst = g_chain + grow * 128 + (lane - 16) * 8;
        ((float4*)dst)[0] = w0;
        ((float4*)dst)[1] = w1;
    }
}

// ---------------- generic tiled GEMM C = A*B (row-major) for H ---------------
__global__ void mm_nn(float* __restrict__ Cc, const float* __restrict__ A,
                      const float* __restrict__ B,
                      int Mm, int Nn, int Kk, int lda, int ldb, int ldc)
{
    __shared__ float As[16][17], Bs[16][17];
    int tx = threadIdx.x, ty = threadIdx.y;
    int row = blockIdx.y * 16 + ty, col = blockIdx.x * 16 + tx;
    float acc = 0.f;
    for (int k0 = 0; k0 < Kk; k0 += 16) {
        As[ty][tx] = (row < Mm) ? A[row * lda + k0 + tx] : 0.f;
        Bs[ty][tx] = (col < Nn) ? B[(k0 + ty) * ldb + col] : 0.f;
        __syncthreads();
        #pragma unroll
        for (int kk = 0; kk < 16; kk++) acc += As[ty][kk] * Bs[kk][tx];
        __syncthreads();
    }
    if (row < Mm && col < Nn) Cc[row * ldc + col] = acc;
}

// ---------------- fused doubling step: chain^2, GB extend, P extend ----------
__global__ void fused_double(int s)
{
    int w = 64 << s;
    int t1 = w >> 1;
    int bid = blockIdx.x;
    const float* chain_s = g_chain + s * 16384;
    const float *Ain, *Bin; float* Cout;
    int bx, by, lda, ldb, ldc;
    if (bid < 64) {
        bx = bid & 7; by = bid >> 3;
        Ain = chain_s; Bin = chain_s; Cout = g_chain + (s + 1) * 16384;
        lda = 128; ldb = 128; ldc = 128;
    } else if (bid < 64 + t1) {
        int r = bid - 64; int nt = w >> 4;
        bx = r % nt; by = r / nt;
        Ain = chain_s; Bin = g_GBwide; Cout = g_GBwide + w;
        lda = 128; ldb = OMD; ldc = OMD;
    } else {
        int r = bid - 64 - t1;
        bx = r & 7; by = r >> 3;
        Ain = g_Pstack; Bin = chain_s; Cout = g_Pstack + w * 128;
        lda = 128; ldb = 128; ldc = 128;
    }
    __shared__ float As[16][17], Bs[16][17];
    int tx = threadIdx.x, ty = threadIdx.y;
    int row = by * 16 + ty, col = bx * 16 + tx;
    float acc = 0.f;
    for (int k0 = 0; k0 < 128; k0 += 16) {
        As[ty][tx] = Ain[row * lda + k0 + tx];
        Bs[ty][tx] = Bin[(k0 + ty) * ldb + col];
        __syncthreads();
        #pragma unroll
        for (int kk = 0; kk < 16; kk++) acc += As[ty][kk] * Bs[kk][tx];
        __syncthreads();
    }
    Cout[row * ldc + col] = acc;
}

// ---------------- small helpers ---------------------------------------------
__global__ void copy_kernel(float* __restrict__ dst, const float* __restrict__ src, int n)
{
    int i = blockIdx.x * blockDim.x + threadIdx.x;
    if (i < n) dst[i] = src[i];
}

__global__ void copy_bmat(const float* __restrict__ Bm)
{
    int i = blockIdx.x * blockDim.x + threadIdx.x;
    if (i < 128 * 64) {
        int r = i >> 6, c = i & 63;
        g_GBwide[r * OMD + c] = Bm[i];
    }
}

// permute within 32-float blocks + tf32 round
__global__ void permute_tf32(float* __restrict__ dst, const float* __restrict__ src,
                             int n)
{
    int i = blockIdx.x * blockDim.x + threadIdx.x;
    if (i >= n) return;
    int q = i & 31;
    int j = ((q & 7) << 2) | (q >> 3);       // inverse permutation
    dst[i] = to_tf32(src[(i - q) + j]);
}

// BinjT[n][perm(q)] = tf32( (A^(31-j) B)[n][uu] ),  q = j*64+uu
__global__ void build_binjT()
{
    int n = blockIdx.x;
    for (int q = threadIdx.x; q < OMD; q += blockDim.x) {
        float v = g_GBwide[n * OMD + (31 - (q >> 6)) * 64 + (q & 63)];
        g_BinjT[n * OMD + (q & ~31) + kperm(q & 31)] = to_tf32(v);
    }
}

// Om[p][perm(q)] = (j<i) ? tf32(H_{i-1-j}[o][uu]) : 0   p=(i,o), i,j 0..31
__global__ void build_om()
{
    int p = blockIdx.x;
    int i = p >> 6, o = p & 63;
    size_t base = (size_t)p * OMD;
    for (int q = threadIdx.x; q < OMD; q += blockDim.x) {
        int j = q >> 6, uu = q & 63;
        float v = 0.f;
        if (j < i) v = to_tf32(g_Hstack[(((i - 1 - j) << 6) + o) * 64 + uu]);
        g_Om[base + (q & ~31) + kperm(q & 31)] = v;
    }
}

__global__ void reduce_v()
{
    int i = blockIdx.x * blockDim.x + threadIdx.x;
    if (i < NCH * NXD) {
        float s = 0.f;
        #pragma unroll
        for (int z = 0; z < 4; z++) s += g_Vpart[(size_t)z * NCH * NXD + i];
        g_V[i] = s;
    }
}

// ---------------- chunk-level scan (A^32, 127 steps) -------------------------
__global__ void __launch_bounds__(128) chunk_scan(const float* __restrict__ x0)
{
    extern __shared__ float At[];        // 128*129 floats
    __shared__ float xs[128];
    int b = blockIdx.x, n = threadIdx.x;
    int np = (n & ~31) | kperm(n & 31);
    const float* A32 = g_chain + 5 * NXD * NXD;
    for (int idx = n; idx < 128 * 128; idx += 128) {
        int row = idx >> 7, col = idx & 127;
        At[col * 129 + row] = A32[idx];
    }
    xs[n] = x0[n];
    __syncthreads();
    g_Xp[(b * KCH + 0) * NXD + np] = to_tf32(xs[n]);
    for (int k = 0; k < KCH - 1; k++) {
        float acc = g_V[(b * KCH + k) * NXD + n];
        #pragma unroll 8
        for (int m = 0; m < 128; m++) acc += At[m * 129 + n] * xs[m];
        __syncthreads();
        xs[n] = acc;
        __syncthreads();
        g_Xp[(b * KCH + k + 1) * NXD + np] = to_tf32(acc);
    }
}

// ---------------- main GEMM (U part only): out = Uc * Om^T -------------------
__global__ void __launch_bounds__(256, 2) gemm_mainU_mma(float* __restrict__ out)
{
    extern __shared__ float sm[];
    int t = threadIdx.x, wid = t >> 5, lane = t & 31;
    int ct = 15 - blockIdx.x, rt = blockIdx.y;
    int mwarp = wid >> 2, nwarp = wid & 3;
    int mbase = mwarp * 64, nbase = nwarp * 32;
    int gr = lane >> 2, gc = lane & 3;

    int NC = (2 * ct + 1) * 2;

    int fr = t >> 1, fs = t & 1;
    const float* AgU = g_Utf + (size_t)(rt * 128 + fr) * OMD + fs * 16;
    const float* BgO = g_Om  + (size_t)(ct * 128 + fr) * OMD + fs * 16;

    int ubase = (4 * fs) ^ (fr & 7);
    uint32_t dA0 = smem_u32(sm + fr * 32 + ubase * 4);
    uint32_t dB0 = dA0 + 16384;

    auto issue = [&](int jc) {
        uint32_t off = (uint32_t)(jc % 3) * 32768u;
        uint32_t da = dA0 + off, db = dB0 + off;
        const float* sa = AgU + jc * 32;
        const float* sb = BgO + jc * 32;
        #pragma unroll
        for (int i = 0; i < 4; i++) {
            cp16(da ^ (i << 4), sa + i * 4);
            cp16(db ^ (i << 4), sb + i * 4);
        }
        asm volatile("cp.async.commit_group;" ::: "memory");
    };

    float acc[4][4][4] = {};
    int su = (2 * gc) ^ gr;

    issue(0);
    if (NC > 1) issue(1);

    for (int ic = 0; ic < NC; ic++) {
        if (ic + 2 < NC) { issue(ic + 2);
            asm volatile("cp.async.wait_group 2;" ::: "memory"); }
        else if (ic + 1 < NC)
            asm volatile("cp.async.wait_group 1;" ::: "memory");
        else
            asm volatile("cp.async.wait_group 0;" ::: "memory");
        __syncthreads();

        const float4* As4 = (const float4*)(sm + (ic % 3) * STG_F);
        const float4* Bs4 = As4 + 1024;
        #pragma unroll
        for (int h = 0; h < 2; h++) {
            int suh = su ^ h;
            float4 av[4][2], bv[4];
            #pragma unroll
            for (int mt = 0; mt < 4; mt++) {
                av[mt][0] = As4[(mbase + mt * 16 + gr) * 8 + suh];
                av[mt][1] = As4[(mbase + mt * 16 + 8 + gr) * 8 + suh];
            }
            #pragma unroll
            for (int nt = 0; nt < 4; nt++)
                bv[nt] = Bs4[(nbase + nt * 8 + gr) * 8 + suh];
            #pragma unroll
            for (int s2 = 0; s2 < 2; s2++) {
                #pragma unroll
                for (int mt = 0; mt < 4; mt++) {
                    const float* a0p = (const float*)&av[mt][0];
                    const float* a1p = (const float*)&av[mt][1];
                    #pragma unroll
                    for (int nt = 0; nt < 4; nt++) {
                        const float* bp = (const float*)&bv[nt];
                        mma8(acc[mt][nt], a0p[2*s2], a1p[2*s2],
                             a0p[2*s2+1], a1p[2*s2+1], bp[2*s2], bp[2*s2+1]);
                    }
                }
            }
        }
        __syncthreads();
    }

    #pragma unroll
    for (int mt = 0; mt < 4; mt++) {
        int rg0 = rt * 128 + mbase + mt * 16 + gr;
        int rg1 = rg0 + 8;
        float* base0 = out + (size_t)rg0 * OMD;
        float* base1 = out + (size_t)rg1 * OMD;
        #pragma unroll
        for (int nt = 0; nt < 4; nt++) {
            int p = ct * 128 + nbase + nt * 8 + 2 * gc;
            float2 w0 = {acc[mt][nt][0], acc[mt][nt][1]};
            float2 w1 = {acc[mt][nt][2], acc[mt][nt][3]};
            *(float2*)(base0 + p) = w0;
            *(float2*)(base1 + p) = w1;
        }
    }
}

// ---------------- tail GEMM: out += Xp * Ptf^T (K = 128) ---------------------
__global__ void __launch_bounds__(256, 2) gemm_tail_mma(float* __restrict__ out)
{
    extern __shared__ float sm[];
    int t = threadIdx.x, wid = t >> 5, lane = t & 31;
    int ct = blockIdx.x, rt = blockIdx.y;
    int mwarp = wid >> 2, nwarp = wid & 3;
    int mbase = mwarp * 64, nbase = nwarp * 32;
    int gr = lane >> 2, gc = lane & 3;
    const int NC = 4;

    int fr = t >> 1, fs = t & 1;
    const float* Ag = g_Xp  + (rt * 128 + fr) * NXD + fs * 16;
    const float* Bg = g_Ptf + (ct * 128 + fr) * NXD + fs * 16;

    int ubase = (4 * fs) ^ (fr & 7);
    uint32_t dA0 = smem_u32(sm + fr * 32 + ubase * 4);
    uint32_t dB0 = dA0 + 16384;

    auto issue = [&](int jc) {
        uint32_t off = (uint32_t)(jc % 3) * 32768u;
        uint32_t da = dA0 + off, db = dB0 + off;
        const float* sa = Ag + jc * 32;
        const float* sb = Bg + jc * 32;
        #pragma unroll
        for (int i = 0; i < 4; i++) {
            cp16(da ^ (i << 4), sa + i * 4);
            cp16(db ^ (i << 4), sb + i * 4);
        }
        asm volatile("cp.async.commit_group;" ::: "memory");
    };

    float acc[4][4][4] = {};
    int su = (2 * gc) ^ gr;

    issue(0); issue(1);
    for (int ic = 0; ic < NC; ic++) {
        if (ic + 2 < NC) { issue(ic + 2);
            asm volatile("cp.async.wait_group 2;" ::: "memory"); }
        else if (ic + 1 < NC)
            asm volatile("cp.async.wait_group 1;" ::: "memory");
        else
            asm volatile("cp.async.wait_group 0;" ::: "memory");
        __syncthreads();

        const float4* As4 = (const float4*)(sm + (ic % 3) * STG_F);
        const float4* Bs4 = As4 + 1024;
        #pragma unroll
        for (int h = 0; h < 2; h++) {
            int suh = su ^ h;
            float4 av[4][2], bv[4];
            #pragma unroll
            for (int mt = 0; mt < 4; mt++) {
                av[mt][0] = As4[(mbase + mt * 16 + gr) * 8 + suh];
                av[mt][1] = As4[(mbase + mt * 16 + 8 + gr) * 8 + suh];
            }
            #pragma unroll
            for (int nt = 0; nt < 4; nt++)
                bv[nt] = Bs4[(nbase + nt * 8 + gr) * 8 + suh];
            #pragma unroll
            for (int s2 = 0; s2 < 2; s2++) {
                #pragma unroll
                for (int mt = 0; mt < 4; mt++) {
                    const float* a0p = (const float*)&av[mt][0];
                    const float* a1p = (const float*)&av[mt][1];
                    #pragma unroll
                    for (int nt = 0; nt < 4; nt++) {
                        const float* bp = (const float*)&bv[nt];
                        mma8(acc[mt][nt], a0p[2*s2], a1p[2*s2],
                             a0p[2*s2+1], a1p[2*s2+1], bp[2*s2], bp[2*s2+1]);
                    }
                }
            }
        }
        __syncthreads();
    }

    #pragma unroll
    for (int mt = 0; mt < 4; mt++) {
        int rg0 = rt * 128 + mbase + mt * 16 + gr;
        int rg1 = rg0 + 8;
        float* base0 = out + (size_t)rg0 * OMD;
        float* base1 = out + (size_t)rg1 * OMD;
        #pragma unroll
        for (int nt = 0; nt < 4; nt++) {
            int p = ct * 128 + nbase + nt * 8 + 2 * gc;
            float2 o0 = *(float2*)(base0 + p);
            float2 o1 = *(float2*)(base1 + p);
            o0.x += acc[mt][nt][0]; o0.y += acc[mt][nt][1];
            o1.x += acc[mt][nt][2]; o1.y += acc[mt][nt][3];
            *(float2*)(base0 + p) = o0;
            *(float2*)(base1 + p) = o1;
        }
    }
}

// ---------------- injection GEMM: 256 threads / 8 warps, 2 CTAs/SM -----------
__global__ void __launch_bounds__(256, 2) gemm_v_mma()
{
    extern __shared__ float sm[];
    int t = threadIdx.x, wid = t >> 5, lane = t & 31;
    int z = blockIdx.x, rt = blockIdx.y;
    int mwarp = wid >> 2, nwarp = wid & 3;
    int mbase = mwarp * 64, nbase = nwarp * 32;
    int gr = lane >> 2, gc = lane & 3;
    const int NC = 16;

    int fr = t >> 1, fs = t & 1;
    const float* Ag = g_Utf + (size_t)(rt * 128 + fr) * OMD + z * 512 + fs * 16;
    const float* Bg = g_BinjT + (size_t)fr * OMD + z * 512 + fs * 16;

    int ubase = (4 * fs) ^ (fr & 7);
    uint32_t dA0 = smem_u32(sm + fr * 32 + ubase * 4);
    uint32_t dB0 = dA0 + 16384;

    auto issue = [&](int jc) {
        uint32_t off = (uint32_t)(jc % 3) * 32768u;
        uint32_t da = dA0 + off, db = dB0 + off;
        const float* sa = Ag + jc * 32;
        const float* sb = Bg + jc * 32;
        #pragma unroll
        for (int i = 0; i < 4; i++) {
            cp16(da ^ (i << 4), sa + i * 4);
            cp16(db ^ (i << 4), sb + i * 4);
        }
        asm volatile("cp.async.commit_group;" ::: "memory");
    };

    float acc[4][4][4] = {};
    int su = (2 * gc) ^ gr;

    issue(0); issue(1);
    for (int ic = 0; ic < NC; ic++) {
        if (ic + 2 < NC) { issue(ic + 2);
            asm volatile("cp.async.wait_group 2;" ::: "memory"); }
        else if (ic + 1 < NC)
            asm volatile("cp.async.wait_group 1;" ::: "memory");
        else
            asm volatile("cp.async.wait_group 0;" ::: "memory");
        __syncthreads();

        const float4* As4 = (const float4*)(sm + (ic % 3) * STG_F);
        const float4* Bs4 = As4 + 1024;
        #pragma unroll
        for (int h = 0; h < 2; h++) {
            int suh = su ^ h;
            float4 av[4][2], bv[4];
            #pragma unroll
            for (int mt = 0; mt < 4; mt++) {
                av[mt][0] = As4[(mbase + mt * 16 + gr) * 8 + suh];
                av[mt][1] = As4[(mbase + mt * 16 + 8 + gr) * 8 + suh];
            }
            #pragma unroll
            for (int nt = 0; nt < 4; nt++)
                bv[nt] = Bs4[(nbase + nt * 8 + gr) * 8 + suh];
            #pragma unroll
            for (int s2 = 0; s2 < 2; s2++) {
                #pragma unroll
                for (int mt = 0; mt < 4; mt++) {
                    const float* a0p = (const float*)&av[mt][0];
                    const float* a1p = (const float*)&av[mt][1];
                    #pragma unroll
                    for (int nt = 0; nt < 4; nt++) {
                        const float* bp = (const float*)&bv[nt];
                        mma8(acc[mt][nt], a0p[2*s2], a1p[2*s2],
                             a0p[2*s2+1], a1p[2*s2+1], bp[2*s2], bp[2*s2+1]);
                    }
                }
            }
        }
        __syncthreads();
    }

    float* Vp = g_Vpart + (size_t)z * NCH * NXD;
    #pragma unroll
    for (int mt = 0; mt < 4; mt++) {
        int rg0 = rt * 128 + mbase + mt * 16 + gr;
        int rg1 = rg0 + 8;
        #pragma unroll
        for (int nt = 0; nt < 4; nt++) {
            int col = nbase + nt * 8 + 2 * gc;
            float2 w0 = {acc[mt][nt][0], acc[mt][nt][1]};
            float2 w1 = {acc[mt][nt][2], acc[mt][nt][3]};
            *(float2*)(Vp + (size_t)rg0 * NXD + col) = w0;
            *(float2*)(Vp + (size_t)rg1 * NXD + col) = w1;
        }
    }
}

// ---------------- host launcher ---------------------------------------------
extern "C" void kernel_launch(void* const* d_in, const int* in_sizes, int n_in,
                              void* d_out, int out_size)
{
    const float* u   = (const float*)d_in[0];
    const float* M   = (const float*)d_in[1];
    const float* Bm  = (const float*)d_in[2];
    const float* C   = (const float*)d_in[3];
    const float* x0  = (const float*)d_in[4];
    float* out = (float*)d_out;

    float *pP, *pPtf, *pH, *pUtf;
    cudaGetSymbolAddress((void**)&pP, g_Pstack);
    cudaGetSymbolAddress((void**)&pPtf, g_Ptf);
    cudaGetSymbolAddress((void**)&pH, g_Hstack);
    cudaGetSymbolAddress((void**)&pUtf, g_Utf);

    static cudaStream_t s2 = nullptr;
    static cudaEvent_t e0 = nullptr, e2 = nullptr, e3 = nullptr, e4 = nullptr;
    if (s2 == nullptr) {
        cudaStreamCreateWithFlags(&s2, cudaStreamNonBlocking);
        cudaEventCreateWithFlags(&e0, cudaEventDisableTiming);
        cudaEventCreateWithFlags(&e2, cudaEventDisableTiming);
        cudaEventCreateWithFlags(&e3, cudaEventDisableTiming);
        cudaEventCreateWithFlags(&e4, cudaEventDisableTiming);
        cudaFuncSetAttribute(gemm_mainU_mma,
                             cudaFuncAttributeMaxDynamicSharedMemorySize, 98304);
        cudaFuncSetAttribute(gemm_tail_mma,
                             cudaFuncAttributeMaxDynamicSharedMemorySize, 98304);
        cudaFuncSetAttribute(gemm_v_mma,
                             cudaFuncAttributeMaxDynamicSharedMemorySize, 98304);
        cudaFuncSetAttribute(chunk_scan,
                             cudaFuncAttributeMaxDynamicSharedMemorySize, 66048);
    }

    // ---- fork: U permute runs on s2 concurrently with the solve chain ----
    cudaEventRecord(e0, 0);
    cudaStreamWaitEvent(s2, e0, 0);
    permute_tf32<<<(NB * TLEN * 64) / 256, 256, 0, s2>>>(pUtf, u, NB * TLEN * 64);
    cudaEventRecord(e4, s2);

    // ---- default stream: A-matrix chain ----
    copy_bmat<<<32, 256>>>(Bm);                 // GB block 0
    copy_kernel<<<32, 256>>>(pP, C, 64 * 128);  // P block 0 = C
    ef_kernel<<<dim3(4, 4), dim3(32, 32)>>>(M);
    solve_kernel<<<8, 512>>>();

    for (int s = 0; s < 5; s++) {
        int w = 64 << s;
        fused_double<<<64 + w, dim3(16, 16)>>>(s);
    }

    mm_nn<<<dim3(4, 128), dim3(16, 16)>>>(pH, pP, Bm, OMD, 64, 128, 128, 64, 64);
    permute_tf32<<<(OMD * NXD) / 256, 256>>>(pPtf, pP, OMD * NXD);
    build_om<<<OMD, 256>>>();
    build_binjT<<<128, 256>>>();

    // ---- fork: injection chain on s2 concurrently with the main GEMM ----
    cudaEventRecord(e2, 0);
    cudaStreamWaitEvent(s2, e2, 0);
    gemm_v_mma<<<dim3(4, 32), 256, 98304, s2>>>();
    reduce_v<<<2048, 256, 0, s2>>>();
    chunk_scan<<<32, 128, 66048, s2>>>(x0);
    cudaEventRecord(e3, s2);

    // ---- default stream: main GEMM (U part), then join, then tail ----
    cudaStreamWaitEvent(0, e4, 0);
    gemm_mainU_mma<<<dim3(16, 32), 256, 98304>>>(out);
    cudaStreamWaitEvent(0, e3, 0);
    gemm_tail_mma<<<dim3(16, 32), 256, 98304>>>(out);
}

// round 17
// speedup vs baseline: 1.9178x; 1.0891x over previous
#include <cuda_runtime.h>
#include <cstdint>
#include <cstddef>

#define NXD  128
#define TLEN 4096
#define NB   32
#define LCH  32
#define KCH  128
#define NCH  (NB*KCH)     // 4096 (batch, chunk) rows
#define OMD  2048         // LCH*64 : Omega dim, Y cols per (b,chunk) row
#define STG_F 8192        // floats per pipeline stage (A 4096 + B 4096)

// ---------------- static device workspaces ----------------------------------
__device__ float g_E[NXD*NXD];
__device__ float g_F[NXD*NXD];
__device__ float g_EFp[4][2][NXD*NXD];        // ef split-K partials
__device__ float g_chain[7*NXD*NXD];          // A^(2^s), s=0..5 used
__device__ float g_Pstack[OMD*NXD];           // P_i = C A^i (raw fp32), 2048x128
__device__ float g_Ptf[OMD*NXD];              // P permuted + tf32
__device__ float g_GBwide[NXD*OMD];           // [A^m B] blocks (128 x 2048)
__device__ float g_BinjT[NXD*OMD];            // injection op^T, permuted+tf32
__device__ float g_Hstack[OMD*64];            // H_m = C A^m B (2048 x 64)
__device__ float g_Om[(size_t)OMD*OMD];       // Omega, permuted+tf32 (16MB)
__device__ float g_Utf[(size_t)NB*TLEN*64];   // U permuted + tf32 (32MB)
__device__ float g_V[NCH*NXD];
__device__ float g_Xp[NCH*NXD];               // chunk states, permuted+tf32
__device__ float g_Vpart[4*NCH*NXD];
__device__ float g_prow[128*256];             // scaled pivot rows
__device__ unsigned g_seq[128];               // pivot publication flags

// ---------------- helpers ----------------------------------------------------
__device__ __forceinline__ float to_tf32(float x) {
    uint32_t u;
    asm("cvt.rna.tf32.f32 %0, %1;" : "=r"(u) : "f"(x));
    return __uint_as_float(u);
}
__device__ __forceinline__ uint32_t smem_u32(const void* p) {
    uint32_t a;
    asm("{ .reg .u64 t; cvta.to.shared.u64 t, %1; cvt.u32.u64 %0, t; }"
        : "=r"(a) : "l"(p));
    return a;
}
__device__ __forceinline__ void mma8(float* c, float a0, float a1, float a2,
                                     float a3, float b0, float b1) {
    asm volatile(
        "mma.sync.aligned.m16n8k8.row.col.f32.tf32.tf32.f32 "
        "{%0,%1,%2,%3}, {%4,%5,%6,%7}, {%8,%9}, {%0,%1,%2,%3};"
        : "+f"(c[0]), "+f"(c[1]), "+f"(c[2]), "+f"(c[3])
        : "r"(__float_as_uint(a0)), "r"(__float_as_uint(a1)),
          "r"(__float_as_uint(a2)), "r"(__float_as_uint(a3)),
          "r"(__float_as_uint(b0)), "r"(__float_as_uint(b1)));
}
__device__ __forceinline__ void cp16(uint32_t dst, const float* src) {
    asm volatile("cp.async.cg.shared.global [%0], [%1], 16;"
                 :: "r"(dst), "l"(src));
}
// permutation: source k (within 32-block) stored at pos (k%4)*8 + k/4
__device__ __forceinline__ int kperm(int j) { return ((j & 3) << 3) | (j >> 2); }

// ---------------- E, F partials from M (split-K x4) --------------------------
__global__ void ef_part(const float* __restrict__ M)
{
    __shared__ float s0i[32][33], s1i[32][33], s0j[32][33], s1j[32][33];
    int tx = threadIdx.x, ty = threadIdx.y;
    int i0 = blockIdx.y * 32, j0 = blockIdx.x * 32;
    int z = blockIdx.z;
    float e0 = 0.f, e1 = 0.f, f = 0.f;
    for (int kt = z * 64; kt < z * 64 + 64; kt += 32) {
        s0i[ty][tx] = M[(i0 + ty) * 256 + kt + tx];
        s1i[ty][tx] = M[(128 + i0 + ty) * 256 + kt + tx];
        s0j[ty][tx] = M[(j0 + ty) * 256 + kt + tx];
        s1j[ty][tx] = M[(128 + j0 + ty) * 256 + kt + tx];
        __syncthreads();
        #pragma unroll
        for (int kk = 0; kk < 32; kk++) {
            float a0 = s0i[ty][kk], a1 = s1i[ty][kk];
            float b0 = s0j[tx][kk], b1 = s1j[tx][kk];
            e0 += a0 * b0; e1 += a1 * b1; f += a1 * b0;
        }
        __syncthreads();
    }
    int i = i0 + ty, j = j0 + tx;
    g_EFp[z][0][i * NXD + j] = e0 + e1;
    g_EFp[z][1][i * NXD + j] = f;
}

__global__ void reduce_ef()
{
    int idx = blockIdx.x * blockDim.x + threadIdx.x;   // 0..16383
    float e = 0.f, f = 0.f;
    #pragma unroll
    for (int z = 0; z < 4; z++) {
        e += g_EFp[z][0][idx];
        f += g_EFp[z][1][idx];
    }
    e *= 0.5f;
    if ((idx >> 7) == (idx & 127)) e += 1e-9f;
    g_E[idx] = e;
    g_F[idx] = f;
}

// ---------------- 8-CTA warp-per-row pipelined Gauss-Jordan (R16 proven) -----
__global__ void __launch_bounds__(512) solve_kernel()
{
    int t = threadIdx.x;
    int wr = t >> 5, lane = t & 31;
    int grow = blockIdx.x * 16 + wr;

    float4 w0, w1;
    {
        const float* base = (lane < 16) ? (g_E + grow * 128 + lane * 8)
                                        : (g_F + grow * 128 + (lane - 16) * 8);
        w0 = ((const float4*)base)[0];
        w1 = ((const float4*)base)[1];
    }

    for (int k = 0; k < 128; k++) {
        int srcl = k >> 3, comp = k & 7;
        float myk;
        {
            float4 v = (comp < 4) ? w0 : w1;
            int c2 = comp & 3;
            myk = (c2 == 0) ? v.x : (c2 == 1) ? v.y : (c2 == 2) ? v.z : v.w;
        }
        float fac = __shfl_sync(0xFFFFFFFFu, myk, srcl);

        if (grow == k) {
            float r;
            asm("rcp.approx.f32 %0, %1;" : "=f"(r) : "f"(fac));
            r = r * (2.0f - fac * r);
            r = r * (2.0f - fac * r);
            w0.x *= r; w0.y *= r; w0.z *= r; w0.w *= r;
            w1.x *= r; w1.y *= r; w1.z *= r; w1.w *= r;
            float* pr = g_prow + k * 256 + lane * 8;
            ((float4*)pr)[0] = w0;
            ((float4*)pr)[1] = w1;
            __syncwarp();
            if (lane == 0) {
                asm volatile("fence.acq_rel.gpu;" ::: "memory");
                asm volatile("st.relaxed.gpu.b32 [%0], %1;"
                             :: "l"(g_seq + k), "r"((unsigned)(k + 1)) : "memory");
            }
        } else {
            unsigned v;
            const unsigned* fp = g_seq + k;
            do {
                asm volatile("ld.acquire.gpu.b32 %0, [%1];"
                             : "=r"(v) : "l"(fp) : "memory");
            } while (v != (unsigned)(k + 1));
            const float* pr = g_prow + k * 256 + lane * 8;
            float4 p0 = ((const float4*)pr)[0];
            float4 p1 = ((const float4*)pr)[1];
            w0.x -= fac * p0.x; w0.y -= fac * p0.y;
            w0.z -= fac * p0.z; w0.w -= fac * p0.w;
            w1.x -= fac * p1.x; w1.y -= fac * p1.y;
            w1.z -= fac * p1.z; w1.w -= fac * p1.w;
        }
    }

    if (lane >= 16) {
        float* dst = g_chain + grow * 128 + (lane - 16) * 8;
        ((float4*)dst)[0] = w0;
        ((float4*)dst)[1] = w1;
    }
}

// ---------------- generic tiled GEMM C = A*B (row-major) for H ---------------
__global__ void mm_nn(float* __restrict__ Cc, const float* __restrict__ A,
                      const float* __restrict__ B,
                      int Mm, int Nn, int Kk, int lda, int ldb, int ldc)
{
    __shared__ float As[16][17], Bs[16][17];
    int tx = threadIdx.x, ty = threadIdx.y;
    int row = blockIdx.y * 16 + ty, col = blockIdx.x * 16 + tx;
    float acc = 0.f;
    for (int k0 = 0; k0 < Kk; k0 += 16) {
        As[ty][tx] = (row < Mm) ? A[row * lda + k0 + tx] : 0.f;
        Bs[ty][tx] = (col < Nn) ? B[(k0 + ty) * ldb + col] : 0.f;
        __syncthreads();
        #pragma unroll
        for (int kk = 0; kk < 16; kk++) acc += As[ty][kk] * Bs[kk][tx];
        __syncthreads();
    }
    if (row < Mm && col < Nn) Cc[row * ldc + col] = acc;
}

// ---------------- fused doubling step: 32x32 tiles, 2x2 accs -----------------
// chain^2 (16 tiles), GB extend (w/8 tiles), P extend (w/8 tiles); K = 128.
__global__ void __launch_bounds__(256) fused_double(int s)
{
    int w = 64 << s;
    int gb_t = w >> 3;               // (128/32) * (w/32)
    int bid = blockIdx.x;
    const float* chain_s = g_chain + s * 16384;
    const float *Ain, *Bin; float* Cout;
    int bx, by, lda, ldb, ldc;
    if (bid < 16) {
        bx = bid & 3; by = bid >> 2;
        Ain = chain_s; Bin = chain_s; Cout = g_chain + (s + 1) * 16384;
        lda = 128; ldb = 128; ldc = 128;
    } else if (bid < 16 + gb_t) {
        int r = bid - 16; int ntx = w >> 5;
        bx = r % ntx; by = r / ntx;
        Ain = chain_s; Bin = g_GBwide; Cout = g_GBwide + w;
        lda = 128; ldb = OMD; ldc = OMD;
    } else {
        int r = bid - 16 - gb_t;
        bx = r & 3; by = r >> 2;
        Ain = g_Pstack; Bin = chain_s; Cout = g_Pstack + w * 128;
        lda = 128; ldb = 128; ldc = 128;
    }
    __shared__ float As[32][33], Bs[32][33];
    int t = threadIdx.x;
    int tx = t & 15, ty = t >> 4;
    int row0 = by * 32, col0 = bx * 32;
    float acc[2][2] = {};
    for (int k0 = 0; k0 < 128; k0 += 32) {
        #pragma unroll
        for (int l = 0; l < 4; l++) {
            int idx = t + l * 256;
            int r = idx >> 5, c = idx & 31;
            As[r][c] = Ain[(row0 + r) * lda + k0 + c];
            Bs[r][c] = Bin[(k0 + r) * ldb + col0 + c];
        }
        __syncthreads();
        #pragma unroll
        for (int kk = 0; kk < 32; kk++) {
            float a0 = As[ty][kk], a1 = As[ty + 16][kk];
            float b0 = Bs[kk][tx], b1 = Bs[kk][tx + 16];
            acc[0][0] += a0 * b0; acc[0][1] += a0 * b1;
            acc[1][0] += a1 * b0; acc[1][1] += a1 * b1;
        }
        __syncthreads();
    }
    Cout[(row0 + ty) * ldc + col0 + tx]           = acc[0][0];
    Cout[(row0 + ty) * ldc + col0 + 16 + tx]      = acc[0][1];
    Cout[(row0 + 16 + ty) * ldc + col0 + tx]      = acc[1][0];
    Cout[(row0 + 16 + ty) * ldc + col0 + 16 + tx] = acc[1][1];
}

// ---------------- small helpers ---------------------------------------------
__global__ void copy_kernel(float* __restrict__ dst, const float* __restrict__ src, int n)
{
    int i = blockIdx.x * blockDim.x + threadIdx.x;
    if (i < n) dst[i] = src[i];
}

__global__ void copy_bmat(const float* __restrict__ Bm)
{
    int i = blockIdx.x * blockDim.x + threadIdx.x;
    if (i < 128 * 64) {
        int r = i >> 6, c = i & 63;
        g_GBwide[r * OMD + c] = Bm[i];
    }
}

// permute within 32-float blocks + tf32 round
__global__ void permute_tf32(float* __restrict__ dst, const float* __restrict__ src,
                             int n)
{
    int i = blockIdx.x * blockDim.x + threadIdx.x;
    if (i >= n) return;
    int q = i & 31;
    int j = ((q & 7) << 2) | (q >> 3);       // inverse permutation
    dst[i] = to_tf32(src[(i - q) + j]);
}

// BinjT[n][perm(q)] = tf32( (A^(31-j) B)[n][uu] ),  q = j*64+uu
__global__ void build_binjT()
{
    int n = blockIdx.x;
    for (int q = threadIdx.x; q < OMD; q += blockDim.x) {
        float v = g_GBwide[n * OMD + (31 - (q >> 6)) * 64 + (q & 63)];
        g_BinjT[n * OMD + (q & ~31) + kperm(q & 31)] = to_tf32(v);
    }
}

// Om[p][perm(q)] = (j<i) ? tf32(H_{i-1-j}[o][uu]) : 0   p=(i,o), i,j 0..31
__global__ void build_om()
{
    int p = blockIdx.x;
    int i = p >> 6, o = p & 63;
    size_t base = (size_t)p * OMD;
    for (int q = threadIdx.x; q < OMD; q += blockDim.x) {
        int j = q >> 6, uu = q & 63;
        float v = 0.f;
        if (j < i) v = to_tf32(g_Hstack[(((i - 1 - j) << 6) + o) * 64 + uu]);
        g_Om[base + (q & ~31) + kperm(q & 31)] = v;
    }
}

__global__ void reduce_v()
{
    int i = blockIdx.x * blockDim.x + threadIdx.x;
    if (i < NCH * NXD) {
        float s = 0.f;
        #pragma unroll
        for (int z = 0; z < 4; z++) s += g_Vpart[(size_t)z * NCH * NXD + i];
        g_V[i] = s;
    }
}

// ---------------- chunk-level scan (A^32, 127 steps) -------------------------
__global__ void __launch_bounds__(128) chunk_scan(const float* __restrict__ x0)
{
    extern __shared__ float At[];        // 128*129 floats
    __shared__ float xs[128];
    int b = blockIdx.x, n = threadIdx.x;
    int np = (n & ~31) | kperm(n & 31);
    const float* A32 = g_chain + 5 * NXD * NXD;
    for (int idx = n; idx < 128 * 128; idx += 128) {
        int row = idx >> 7, col = idx & 127;
        At[col * 129 + row] = A32[idx];
    }
    xs[n] = x0[n];
    __syncthreads();
    g_Xp[(b * KCH + 0) * NXD + np] = to_tf32(xs[n]);
    for (int k = 0; k < KCH - 1; k++) {
        float acc = g_V[(b * KCH + k) * NXD + n];
        #pragma unroll 8
        for (int m = 0; m < 128; m++) acc += At[m * 129 + n] * xs[m];
        __syncthreads();
        xs[n] = acc;
        __syncthreads();
        g_Xp[(b * KCH + k + 1) * NXD + np] = to_tf32(acc);
    }
}

// ---------------- main GEMM (U part only): out = Uc * Om^T -------------------
__global__ void __launch_bounds__(256, 2) gemm_mainU_mma(float* __restrict__ out)
{
    extern __shared__ float sm[];
    int t = threadIdx.x, wid = t >> 5, lane = t & 31;
    int ct = 15 - blockIdx.x, rt = blockIdx.y;
    int mwarp = wid >> 2, nwarp = wid & 3;
    int mbase = mwarp * 64, nbase = nwarp * 32;
    int gr = lane >> 2, gc = lane & 3;

    int NC = (2 * ct + 1) * 2;

    int fr = t >> 1, fs = t & 1;
    const float* AgU = g_Utf + (size_t)(rt * 128 + fr) * OMD + fs * 16;
    const float* BgO = g_Om  + (size_t)(ct * 128 + fr) * OMD + fs * 16;

    int ubase = (4 * fs) ^ (fr & 7);
    uint32_t dA0 = smem_u32(sm + fr * 32 + ubase * 4);
    uint32_t dB0 = dA0 + 16384;

    auto issue = [&](int jc) {
        uint32_t off = (uint32_t)(jc % 3) * 32768u;
        uint32_t da = dA0 + off, db = dB0 + off;
        const float* sa = AgU + jc * 32;
        const float* sb = BgO + jc * 32;
        #pragma unroll
        for (int i = 0; i < 4; i++) {
            cp16(da ^ (i << 4), sa + i * 4);
            cp16(db ^ (i << 4), sb + i * 4);
        }
        asm volatile("cp.async.commit_group;" ::: "memory");
    };

    float acc[4][4][4] = {};
    int su = (2 * gc) ^ gr;

    issue(0);
    if (NC > 1) issue(1);

    for (int ic = 0; ic < NC; ic++) {
        if (ic + 2 < NC) { issue(ic + 2);
            asm volatile("cp.async.wait_group 2;" ::: "memory"); }
        else if (ic + 1 < NC)
            asm volatile("cp.async.wait_group 1;" ::: "memory");
        else
            asm volatile("cp.async.wait_group 0;" ::: "memory");
        __syncthreads();

        const float4* As4 = (const float4*)(sm + (ic % 3) * STG_F);
        const float4* Bs4 = As4 + 1024;
        #pragma unroll
        for (int h = 0; h < 2; h++) {
            int suh = su ^ h;
            float4 av[4][2], bv[4];
            #pragma unroll
            for (int mt = 0; mt < 4; mt++) {
                av[mt][0] = As4[(mbase + mt * 16 + gr) * 8 + suh];
                av[mt][1] = As4[(mbase + mt * 16 + 8 + gr) * 8 + suh];
            }
            #pragma unroll
            for (int nt = 0; nt < 4; nt++)
                bv[nt] = Bs4[(nbase + nt * 8 + gr) * 8 + suh];
            #pragma unroll
            for (int s2 = 0; s2 < 2; s2++) {
                #pragma unroll
                for (int mt = 0; mt < 4; mt++) {
                    const float* a0p = (const float*)&av[mt][0];
                    const float* a1p = (const float*)&av[mt][1];
                    #pragma unroll
                    for (int nt = 0; nt < 4; nt++) {
                        const float* bp = (const float*)&bv[nt];
                        mma8(acc[mt][nt], a0p[2*s2], a1p[2*s2],
                             a0p[2*s2+1], a1p[2*s2+1], bp[2*s2], bp[2*s2+1]);
                    }
                }
            }
        }
        __syncthreads();
    }

    #pragma unroll
    for (int mt = 0; mt < 4; mt++) {
        int rg0 = rt * 128 + mbase + mt * 16 + gr;
        int rg1 = rg0 + 8;
        float* base0 = out + (size_t)rg0 * OMD;
        float* base1 = out + (size_t)rg1 * OMD;
        #pragma unroll
        for (int nt = 0; nt < 4; nt++) {
            int p = ct * 128 + nbase + nt * 8 + 2 * gc;
            float2 w0 = {acc[mt][nt][0], acc[mt][nt][1]};
            float2 w1 = {acc[mt][nt][2], acc[mt][nt][3]};
            *(float2*)(base0 + p) = w0;
            *(float2*)(base1 + p) = w1;
        }
    }
}

// ---------------- tail GEMM: out += Xp * Ptf^T (K = 128) ---------------------
__global__ void __launch_bounds__(256, 2) gemm_tail_mma(float* __restrict__ out)
{
    extern __shared__ float sm[];
    int t = threadIdx.x, wid = t >> 5, lane = t & 31;
    int ct = blockIdx.x, rt = blockIdx.y;
    int mwarp = wid >> 2, nwarp = wid & 3;
    int mbase = mwarp * 64, nbase = nwarp * 32;
    int gr = lane >> 2, gc = lane & 3;
    const int NC = 4;

    int fr = t >> 1, fs = t & 1;
    const float* Ag = g_Xp  + (rt * 128 + fr) * NXD + fs * 16;
    const float* Bg = g_Ptf + (ct * 128 + fr) * NXD + fs * 16;

    int ubase = (4 * fs) ^ (fr & 7);
    uint32_t dA0 = smem_u32(sm + fr * 32 + ubase * 4);
    uint32_t dB0 = dA0 + 16384;

    auto issue = [&](int jc) {
        uint32_t off = (uint32_t)(jc % 3) * 32768u;
        uint32_t da = dA0 + off, db = dB0 + off;
        const float* sa = Ag + jc * 32;
        const float* sb = Bg + jc * 32;
        #pragma unroll
        for (int i = 0; i < 4; i++) {
            cp16(da ^ (i << 4), sa + i * 4);
            cp16(db ^ (i << 4), sb + i * 4);
        }
        asm volatile("cp.async.commit_group;" ::: "memory");
    };

    float acc[4][4][4] = {};
    int su = (2 * gc) ^ gr;

    issue(0); issue(1);
    for (int ic = 0; ic < NC; ic++) {
        if (ic + 2 < NC) { issue(ic + 2);
            asm volatile("cp.async.wait_group 2;" ::: "memory"); }
        else if (ic + 1 < NC)
            asm volatile("cp.async.wait_group 1;" ::: "memory");
        else
            asm volatile("cp.async.wait_group 0;" ::: "memory");
        __syncthreads();

        const float4* As4 = (const float4*)(sm + (ic % 3) * STG_F);
        const float4* Bs4 = As4 + 1024;
        #pragma unroll
        for (int h = 0; h < 2; h++) {
            int suh = su ^ h;
            float4 av[4][2], bv[4];
            #pragma unroll
            for (int mt = 0; mt < 4; mt++) {
                av[mt][0] = As4[(mbase + mt * 16 + gr) * 8 + suh];
                av[mt][1] = As4[(mbase + mt * 16 + 8 + gr) * 8 + suh];
            }
            #pragma unroll
            for (int nt = 0; nt < 4; nt++)
                bv[nt] = Bs4[(nbase + nt * 8 + gr) * 8 + suh];
            #pragma unroll
            for (int s2 = 0; s2 < 2; s2++) {
                #pragma unroll
                for (int mt = 0; mt < 4; mt++) {
                    const float* a0p = (const float*)&av[mt][0];
                    const float* a1p = (const float*)&av[mt][1];
                    #pragma unroll
                    for (int nt = 0; nt < 4; nt++) {
                        const float* bp = (const float*)&bv[nt];
                        mma8(acc[mt][nt], a0p[2*s2], a1p[2*s2],
                             a0p[2*s2+1], a1p[2*s2+1], bp[2*s2], bp[2*s2+1]);
                    }
                }
            }
        }
        __syncthreads();
    }

    #pragma unroll
    for (int mt = 0; mt < 4; mt++) {
        int rg0 = rt * 128 + mbase + mt * 16 + gr;
        int rg1 = rg0 + 8;
        float* base0 = out + (size_t)rg0 * OMD;
        float* base1 = out + (size_t)rg1 * OMD;
        #pragma unroll
        for (int nt = 0; nt < 4; nt++) {
            int p = ct * 128 + nbase + nt * 8 + 2 * gc;
            float2 o0 = *(float2*)(base0 + p);
            float2 o1 = *(float2*)(base1 + p);
            o0.x += acc[mt][nt][0]; o0.y += acc[mt][nt][1];
            o1.x += acc[mt][nt][2]; o1.y += acc[mt][nt][3];
            *(float2*)(base0 + p) = o0;
            *(float2*)(base1 + p) = o1;
        }
    }
}

// ---------------- injection GEMM: 256 threads / 8 warps, 2 CTAs/SM -----------
__global__ void __launch_bounds__(256, 2) gemm_v_mma()
{
    extern __shared__ float sm[];
    int t = threadIdx.x, wid = t >> 5, lane = t & 31;
    int z = blockIdx.x, rt = blockIdx.y;
    int mwarp = wid >> 2, nwarp = wid & 3;
    int mbase = mwarp * 64, nbase = nwarp * 32;
    int gr = lane >> 2, gc = lane & 3;
    const int NC = 16;

    int fr = t >> 1, fs = t & 1;
    const float* Ag = g_Utf + (size_t)(rt * 128 + fr) * OMD + z * 512 + fs * 16;
    const float* Bg = g_BinjT + (size_t)fr * OMD + z * 512 + fs * 16;

    int ubase = (4 * fs) ^ (fr & 7);
    uint32_t dA0 = smem_u32(sm + fr * 32 + ubase * 4);
    uint32_t dB0 = dA0 + 16384;

    auto issue = [&](int jc) {
        uint32_t off = (uint32_t)(jc % 3) * 32768u;
        uint32_t da = dA0 + off, db = dB0 + off;
        const float* sa = Ag + jc * 32;
        const float* sb = Bg + jc * 32;
        #pragma unroll
        for (int i = 0; i < 4; i++) {
            cp16(da ^ (i << 4), sa + i * 4);
            cp16(db ^ (i << 4), sb + i * 4);
        }
        asm volatile("cp.async.commit_group;" ::: "memory");
    };

    float acc[4][4][4] = {};
    int su = (2 * gc) ^ gr;

    issue(0); issue(1);
    for (int ic = 0; ic < NC; ic++) {
        if (ic + 2 < NC) { issue(ic + 2);
            asm volatile("cp.async.wait_group 2;" ::: "memory"); }
        else if (ic + 1 < NC)
            asm volatile("cp.async.wait_group 1;" ::: "memory");
        else
            asm volatile("cp.async.wait_group 0;" ::: "memory");
        __syncthreads();

        const float4* As4 = (const float4*)(sm + (ic % 3) * STG_F);
        const float4* Bs4 = As4 + 1024;
        #pragma unroll
        for (int h = 0; h < 2; h++) {
            int suh = su ^ h;
            float4 av[4][2], bv[4];
            #pragma unroll
            for (int mt = 0; mt < 4; mt++) {
                av[mt][0] = As4[(mbase + mt * 16 + gr) * 8 + suh];
                av[mt][1] = As4[(mbase + mt * 16 + 8 + gr) * 8 + suh];
            }
            #pragma unroll
            for (int nt = 0; nt < 4; nt++)
                bv[nt] = Bs4[(nbase + nt * 8 + gr) * 8 + suh];
            #pragma unroll
            for (int s2 = 0; s2 < 2; s2++) {
                #pragma unroll
                for (int mt = 0; mt < 4; mt++) {
                    const float* a0p = (const float*)&av[mt][0];
                    const float* a1p = (const float*)&av[mt][1];
                    #pragma unroll
                    for (int nt = 0; nt < 4; nt++) {
                        const float* bp = (const float*)&bv[nt];
                        mma8(acc[mt][nt], a0p[2*s2], a1p[2*s2],
                             a0p[2*s2+1], a1p[2*s2+1], bp[2*s2], bp[2*s2+1]);
                    }
                }
            }
        }
        __syncthreads();
    }

    float* Vp = g_Vpart + (size_t)z * NCH * NXD;
    #pragma unroll
    for (int mt = 0; mt < 4; mt++) {
        int rg0 = rt * 128 + mbase + mt * 16 + gr;
        int rg1 = rg0 + 8;
        #pragma unroll
        for (int nt = 0; nt < 4; nt++) {
            int col = nbase + nt * 8 + 2 * gc;
            float2 w0 = {acc[mt][nt][0], acc[mt][nt][1]};
            float2 w1 = {acc[mt][nt][2], acc[mt][nt][3]};
            *(float2*)(Vp + (size_t)rg0 * NXD + col) = w0;
            *(float2*)(Vp + (size_t)rg1 * NXD + col) = w1;
        }
    }
}

// ---------------- host launcher ---------------------------------------------
extern "C" void kernel_launch(void* const* d_in, const int* in_sizes, int n_in,
                              void* d_out, int out_size)
{
    const float* u   = (const float*)d_in[0];
    const float* M   = (const float*)d_in[1];
    const float* Bm  = (const float*)d_in[2];
    const float* C   = (const float*)d_in[3];
    const float* x0  = (const float*)d_in[4];
    float* out = (float*)d_out;

    float *pP, *pPtf, *pH, *pUtf;
    cudaGetSymbolAddress((void**)&pP, g_Pstack);
    cudaGetSymbolAddress((void**)&pPtf, g_Ptf);
    cudaGetSymbolAddress((void**)&pH, g_Hstack);
    cudaGetSymbolAddress((void**)&pUtf, g_Utf);

    static cudaStream_t s2 = nullptr;
    static cudaEvent_t e0 = nullptr, e2 = nullptr, e3 = nullptr, e4 = nullptr,
                       eD = nullptr;
    if (s2 == nullptr) {
        cudaStreamCreateWithFlags(&s2, cudaStreamNonBlocking);
        cudaEventCreateWithFlags(&e0, cudaEventDisableTiming);
        cudaEventCreateWithFlags(&e2, cudaEventDisableTiming);
        cudaEventCreateWithFlags(&e3, cudaEventDisableTiming);
        cudaEventCreateWithFlags(&e4, cudaEventDisableTiming);
        cudaEventCreateWithFlags(&eD, cudaEventDisableTiming);
        cudaFuncSetAttribute(gemm_mainU_mma,
                             cudaFuncAttributeMaxDynamicSharedMemorySize, 98304);
        cudaFuncSetAttribute(gemm_tail_mma,
                             cudaFuncAttributeMaxDynamicSharedMemorySize, 98304);
        cudaFuncSetAttribute(gemm_v_mma,
                             cudaFuncAttributeMaxDynamicSharedMemorySize, 98304);
        cudaFuncSetAttribute(chunk_scan,
                             cudaFuncAttributeMaxDynamicSharedMemorySize, 66048);
    }

    // ---- fork: U permute runs on s2 concurrently with the solve chain ----
    cudaEventRecord(e0, 0);
    cudaStreamWaitEvent(s2, e0, 0);
    permute_tf32<<<(NB * TLEN * 64) / 256, 256, 0, s2>>>(pUtf, u, NB * TLEN * 64);
    cudaEventRecord(e4, s2);

    // ---- default stream: A-matrix chain ----
    copy_bmat<<<32, 256>>>(Bm);                 // GB block 0
    copy_kernel<<<32, 256>>>(pP, C, 64 * 128);  // P block 0 = C
    ef_part<<<dim3(4, 4, 4), dim3(32, 32)>>>(M);
    reduce_ef<<<64, 256>>>();
    solve_kernel<<<8, 512>>>();

    for (int s = 0; s < 5; s++) {
        int w = 64 << s;
        fused_double<<<16 + (w >> 2), 256>>>(s);
    }
    cudaEventRecord(eD, 0);

    // ---- s2 after doubling: P permute + BinjT + injection chain ----
    cudaStreamWaitEvent(s2, eD, 0);
    permute_tf32<<<(OMD * NXD) / 256, 256, 0, s2>>>(pPtf, pP, OMD * NXD);
    build_binjT<<<128, 256, 0, s2>>>();
    gemm_v_mma<<<dim3(4, 32), 256, 98304, s2>>>();
    reduce_v<<<2048, 256, 0, s2>>>();
    chunk_scan<<<32, 128, 66048, s2>>>(x0);
    cudaEventRecord(e3, s2);

    // ---- default stream: H, Om, then main GEMM, join, tail ----
    mm_nn<<<dim3(4, 128), dim3(16, 16)>>>(pH, pP, Bm, OMD, 64, 128, 128, 64, 64);
    build_om<<<OMD, 256>>>();
    cudaStreamWaitEvent(0, e4, 0);
    gemm_mainU_mma<<<dim3(16, 32), 256, 98304>>>(out);
    cudaStreamWaitEvent(0, e3, 0);
    gemm_tail_mma<<<dim3(16, 32), 256, 98304>>>(out);
}